// round 6
// baseline (speedup 1.0000x reference)
#include <cuda_runtime.h>
#include <stdint.h>

#define S_LEN 512
#define BATCH 128
#define IDIM  1024
#define HDIM  1024
#define N3    3072       // 3 gates * H, interleaved col = 3*j + gate
#define MTOT  (S_LEN*BATCH)

#define KTB   64         // K-tile bytes (64 int8)
#define ASTRB 80         // smem row stride bytes (64 data + 16 pad)
#define NSTG  3

#define TN_S  48               // step N tile (2 ngrp x 24)
#define TN_G  96               // gi N tile   (2 ngrp x 48)
#define NBLK_S (N3/TN_S)       // 64
#define NBLK_G (N3/TN_G)       // 32

#define APLANE  (128*ASTRB)                 // 10240 B
#define ABYTES  (2*APLANE)                  // hi+lo = 20480 B
#define STAGE_S (ABYTES + 2*TN_S*ASTRB)     // 28160
#define STAGE_G (ABYTES + 2*TN_G*ASTRB)     // 35840
#define SMEM_S  (NSTG*STAGE_S)              // 84480
#define SMEM_G  (NSTG*STAGE_G)              // 107520

typedef signed char i8;

// ---------------- device scratch ----------------
__device__ i8    g_x8h[(size_t)MTOT*IDIM];
__device__ i8    g_x8l[(size_t)MTOT*IDIM];
__device__ i8    g_wih8h[(size_t)2*N3*IDIM];
__device__ i8    g_wih8l[(size_t)2*N3*IDIM];
__device__ i8    g_whh8h[(size_t)2*N3*HDIM];
__device__ i8    g_whh8l[(size_t)2*N3*HDIM];
__device__ i8    g_h8h[2*2*BATCH*HDIM];     // [par][dir][b][j]
__device__ i8    g_h8l[2*2*BATCH*HDIM];
__device__ float g_bias[2][4][HDIM];        // br, bz, b_in, b_hn
__device__ float g_h[2*BATCH*HDIM];         // fp32 recurrent state
__device__ float g_gi[(size_t)2*MTOT*N3];   // precomputed x@Wih^T
__device__ unsigned g_axbits;
__device__ float g_inv_sx, g_scale_gi, g_scale_gh;

// ---------------- helpers ----------------
__device__ __forceinline__ uint32_t smaddr(const void* p) {
    return (uint32_t)__cvta_generic_to_shared(p);
}
__device__ __forceinline__ void cp16(uint32_t d, const void* s) {
    asm volatile("cp.async.cg.shared.global [%0], [%1], 16;\n" :: "r"(d), "l"(s));
}
__device__ __forceinline__ void ldsm_x4(uint32_t r[4], uint32_t a) {
    asm volatile("ldmatrix.sync.aligned.m8n8.x4.shared.b16 {%0,%1,%2,%3},[%4];"
                 : "=r"(r[0]), "=r"(r[1]), "=r"(r[2]), "=r"(r[3]) : "r"(a));
}
__device__ __forceinline__ void imma(int c[4], const uint32_t a[4], uint32_t b0, uint32_t b1) {
    asm volatile(
        "mma.sync.aligned.m16n8k32.row.col.s32.s8.s8.s32 "
        "{%0,%1,%2,%3},{%4,%5,%6,%7},{%8,%9},{%0,%1,%2,%3};"
        : "+r"(c[0]), "+r"(c[1]), "+r"(c[2]), "+r"(c[3])
        : "r"(a[0]), "r"(a[1]), "r"(a[2]), "r"(a[3]), "r"(b0), "r"(b1));
}
__device__ __forceinline__ float fsig(float x) {
    return __fdividef(1.f, 1.f + __expf(-x));
}
__device__ __forceinline__ float ftanh(float x) {
    return 1.f - __fdividef(2.f, __expf(2.f * x) + 1.f);
}
__device__ __forceinline__ void q2(float v, float fullscale, i8& hi, i8& lo) {
    float q = v * fullscale;
    q = fminf(fmaxf(q, -127.f), 127.f);
    float qh = rintf(q);
    float ql = rintf((q - qh) * 128.f);
    hi = (i8)(int)qh; lo = (i8)(int)ql;
}

#define CP_COMMIT() asm volatile("cp.async.commit_group;")

// ---------------- scale kernels ----------------
__global__ void zero_ax_kernel() { if (threadIdx.x == 0) g_axbits = 0u; }

__global__ void absmax_x_kernel(const float* __restrict__ x) {
    unsigned m = 0;
    for (size_t i = (size_t)blockIdx.x * 256 + threadIdx.x; i < (size_t)MTOT * IDIM;
         i += (size_t)gridDim.x * 256)
        m = max(m, __float_as_uint(fabsf(x[i])));
#pragma unroll
    for (int o = 16; o; o >>= 1) m = max(m, __shfl_xor_sync(0xffffffffu, m, o));
    __shared__ unsigned sm[8];
    if ((threadIdx.x & 31) == 0) sm[threadIdx.x >> 5] = m;
    __syncthreads();
    if (threadIdx.x < 8) {
        m = sm[threadIdx.x];
#pragma unroll
        for (int o = 4; o; o >>= 1) m = max(m, __shfl_xor_sync(0xffu, m, o));
        if (threadIdx.x == 0) atomicMax(&g_axbits, m);
    }
}

__global__ void finalize_scales_kernel() {
    float ax = __uint_as_float(g_axbits);
    if (!(ax > 0.f)) ax = 1.f;
    g_inv_sx   = 127.f / ax;
    g_scale_gi = (ax / 127.f) * (1.f / 4064.f);         // s_x * s_w
    g_scale_gh = (1.f / 127.f) * (1.f / 4064.f);        // s_h * s_w
}

// ---------------- pack kernels ----------------
__global__ void pack_x_kernel(const float* __restrict__ x) {
    int i = blockIdx.x * 256 + threadIdx.x;
    i8 hi, lo; q2(x[i], g_inv_sx, hi, lo);
    g_x8h[i] = hi; g_x8l[i] = lo;
}

__global__ void pack_w_kernel(const float* __restrict__ Wih_f, const float* __restrict__ Whh_f,
                              const float* __restrict__ Wih_b, const float* __restrict__ Whh_b) {
    int idx = blockIdx.x * 256 + threadIdx.x;   // over 2 * N3 * 2048
    int k   = idx & 2047;
    int n   = (idx >> 11) % N3;
    int dir = idx / (N3 * 2048);
    int j = n / 3, g = n % 3;
    int srow = g * HDIM + j;
    float v;
    size_t doff;
    i8 *dh, *dl;
    if (k < IDIM) {
        v = (dir ? Wih_b : Wih_f)[srow * IDIM + k];
        doff = ((size_t)dir * N3 + n) * IDIM + k;
        dh = g_wih8h; dl = g_wih8l;
    } else {
        v = (dir ? Whh_b : Whh_f)[srow * HDIM + (k - IDIM)];
        doff = ((size_t)dir * N3 + n) * HDIM + (k - IDIM);
        dh = g_whh8h; dl = g_whh8l;
    }
    i8 hi, lo; q2(v, 4064.f, hi, lo);
    dh[doff] = hi; dl[doff] = lo;
}

__global__ void pack_bias_kernel(const float* __restrict__ bih_f, const float* __restrict__ bhh_f,
                                 const float* __restrict__ bih_b, const float* __restrict__ bhh_b) {
    int i = blockIdx.x * 256 + threadIdx.x;   // 0..2047
    int dir = i >> 10, j = i & 1023;
    const float* bih = dir ? bih_b : bih_f;
    const float* bhh = dir ? bhh_b : bhh_f;
    g_bias[dir][0][j] = bih[j] + bhh[j];
    g_bias[dir][1][j] = bih[HDIM + j] + bhh[HDIM + j];
    g_bias[dir][2][j] = bih[2 * HDIM + j];
    g_bias[dir][3][j] = bhh[2 * HDIM + j];
}

__global__ void init_h_kernel() {
    int i = blockIdx.x * 256 + threadIdx.x;   // 0..262143
    g_h[i] = 0.f;
    if (i < 2 * 2 * BATCH * HDIM / 4) {
        ((int*)g_h8h)[i] = 0;
        ((int*)g_h8l)[i] = 0;
    }
}

// ---------------- mainloop compute: warp = 16 rows x (NT*8) cols ----------------
template<int NT, int BROWS>
__device__ __forceinline__ void compute_i8(uint32_t st, int mwarp, int ngrp, int lane,
                                           int hh[NT][4], int cr[NT][4]) {
    const uint32_t pA  = st + (mwarp * 16 + (lane & 15)) * ASTRB + (lane >> 4) * 16;
    const uint32_t pAl = pA + APLANE;
    const uint32_t pB  = st + ABYTES
                         + (ngrp * (NT * 8) + (lane & 7)) * ASTRB
                         + ((lane >> 3) & 1) * 16
                         + ((lane < 16) ? 0 : BROWS * ASTRB);
#pragma unroll
    for (int ks = 0; ks < 2; ++ks) {
        const int kb = ks * 32;
        uint32_t ah[4], al[4];
        ldsm_x4(ah, pA + kb);
        ldsm_x4(al, pAl + kb);
#pragma unroll
        for (int nt = 0; nt < NT; ++nt) {
            uint32_t b4[4];   // {bhi0, bhi1, blo0, blo1}
            ldsm_x4(b4, pB + nt * 8 * ASTRB + kb);
            imma(hh[nt], ah, b4[0], b4[1]);   // hi*hi
            imma(cr[nt], ah, b4[2], b4[3]);   // hi*lo
            imma(cr[nt], al, b4[0], b4[1]);   // lo*hi
        }
    }
}

// ---------------- pre-GEMM: gi = x @ Wih^T ----------------
// grid: (NBLK_G=32, MTOT/128=512, 2), block 512 (16 warps: 8 M x 2 N)
__global__ void __launch_bounds__(512) gi_gemm() {
    extern __shared__ char smraw[];
    const uint32_t sb = smaddr(smraw);

    const int nblk = blockIdx.x, mblk = blockIdx.y, dir = blockIdx.z;
    const int t = threadIdx.x, warp = t >> 5, lane = t & 31;
    const int mwarp = warp & 7, ngrp = warp >> 3;
    const int grp = lane >> 2, tq = lane & 3;

    auto copy_tile = [&](int kt, int buf) {
        const uint32_t st = sb + buf * STAGE_G;
        const int k0 = kt * KTB;
        {
            int row = t >> 2, kq = (t & 3) * 16;
            size_t off = ((size_t)mblk * 128 + row) * IDIM + k0 + kq;
            cp16(st + row * ASTRB + kq, g_x8h + off);
            cp16(st + APLANE + row * ASTRB + kq, g_x8l + off);
        }
        if (t < 4 * TN_G) {
            int nloc = t >> 2, kq = (t & 3) * 16;
            size_t off = ((size_t)dir * N3 + nblk * TN_G + nloc) * IDIM + k0 + kq;
            cp16(st + ABYTES + nloc * ASTRB + kq, g_wih8h + off);
            cp16(st + ABYTES + TN_G * ASTRB + nloc * ASTRB + kq, g_wih8l + off);
        }
    };

    int hh[6][4], cr[6][4];
#pragma unroll
    for (int i = 0; i < 6; i++)
#pragma unroll
        for (int q = 0; q < 4; q++) { hh[i][q] = 0; cr[i][q] = 0; }

    copy_tile(0, 0); CP_COMMIT();
    copy_tile(1, 1); CP_COMMIT();

    const int NKT = IDIM / KTB;   // 16
#pragma unroll 1
    for (int kt = 0; kt < NKT; ++kt) {
        if (kt < NKT - 1) asm volatile("cp.async.wait_group 1;");
        else              asm volatile("cp.async.wait_group 0;");
        __syncthreads();
        if (kt + 2 < NKT) { copy_tile(kt + 2, (kt + 2) % NSTG); CP_COMMIT(); }
        compute_i8<6, TN_G>(sb + (kt % NSTG) * STAGE_G, mwarp, ngrp, lane, hh, cr);
    }

    // epilogue: combine + scale, write to g_gi
    const float sgi = g_scale_gi;
    const int m0 = mblk * 128 + mwarp * 16 + grp;
    const int colbase = nblk * TN_G + ngrp * 48 + tq * 2;
    float* d0 = g_gi + ((size_t)dir * MTOT + m0) * N3;
    float* d1 = d0 + (size_t)8 * N3;
#pragma unroll
    for (int nt = 0; nt < 6; ++nt) {
        int col = colbase + nt * 8;
        d0[col]     = sgi * ((float)hh[nt][0] + (float)cr[nt][0] * 0.0078125f);
        d0[col + 1] = sgi * ((float)hh[nt][1] + (float)cr[nt][1] * 0.0078125f);
        d1[col]     = sgi * ((float)hh[nt][2] + (float)cr[nt][2] * 0.0078125f);
        d1[col + 1] = sgi * ((float)hh[nt][3] + (float)cr[nt][3] * 0.0078125f);
    }
}

// ---------------- recurrent step: gh = h @ Whh^T, then gates ----------------
// grid: (NBLK_S=64, 2), block 512 (16 warps: 8 M x 2 N)
__global__ void __launch_bounds__(512) gru_step(float* __restrict__ out, int step) {
    extern __shared__ char smraw[];
    const uint32_t sb = smaddr(smraw);

    const int nblk = blockIdx.x, dir = blockIdx.y;
    const int t = threadIdx.x, warp = t >> 5, lane = t & 31;
    const int mwarp = warp & 7, ngrp = warp >> 3;
    const int grp = lane >> 2, tq = lane & 3;
    const int rpar = step & 1, wpar = rpar ^ 1;
    const int s_x  = dir ? (S_LEN - 1 - step) : step;

    auto copy_tile = [&](int kt, int buf) {
        const uint32_t st = sb + buf * STAGE_S;
        const int k0 = kt * KTB;
        {
            int row = t >> 2, kq = (t & 3) * 16;
            int off = ((rpar * 2 + dir) * BATCH + row) * HDIM + k0 + kq;
            cp16(st + row * ASTRB + kq, g_h8h + off);
            cp16(st + APLANE + row * ASTRB + kq, g_h8l + off);
        }
        if (t < 4 * TN_S) {
            int nloc = t >> 2, kq = (t & 3) * 16;
            size_t off = ((size_t)dir * N3 + nblk * TN_S + nloc) * HDIM + k0 + kq;
            cp16(st + ABYTES + nloc * ASTRB + kq, g_whh8h + off);
            cp16(st + ABYTES + TN_S * ASTRB + nloc * ASTRB + kq, g_whh8l + off);
        }
    };

    int hh[3][4], cr[3][4];
#pragma unroll
    for (int i = 0; i < 3; i++)
#pragma unroll
        for (int q = 0; q < 4; q++) { hh[i][q] = 0; cr[i][q] = 0; }

    copy_tile(0, 0); CP_COMMIT();
    copy_tile(1, 1); CP_COMMIT();

    const int NKT = HDIM / KTB;   // 16
#pragma unroll 1
    for (int kt = 0; kt < NKT; ++kt) {
        if (kt < NKT - 1) asm volatile("cp.async.wait_group 1;");
        else              asm volatile("cp.async.wait_group 0;");
        __syncthreads();
        if (kt + 2 < NKT) { copy_tile(kt + 2, (kt + 2) % NSTG); CP_COMMIT(); }
        compute_i8<3, TN_S>(sb + (kt % NSTG) * STAGE_S, mwarp, ngrp, lane, hh, cr);
    }

    // ---- epilogue: combine accumulators -> smem, then GRU gates ----
    __syncthreads();
    float* sC = (float*)smraw;   // [128][49]
    {
        const float sgh = g_scale_gh;
        const int row  = mwarp * 16 + grp;
        const int colb = ngrp * 24 + tq * 2;
#pragma unroll
        for (int nt = 0; nt < 3; ++nt) {
            int col = colb + nt * 8;
            sC[row * 49 + col]           = sgh * ((float)hh[nt][0] + (float)cr[nt][0] * 0.0078125f);
            sC[row * 49 + col + 1]       = sgh * ((float)hh[nt][1] + (float)cr[nt][1] * 0.0078125f);
            sC[(row + 8) * 49 + col]     = sgh * ((float)hh[nt][2] + (float)cr[nt][2] * 0.0078125f);
            sC[(row + 8) * 49 + col + 1] = sgh * ((float)hh[nt][3] + (float)cr[nt][3] * 0.0078125f);
        }
    }
    __syncthreads();

    const size_t gibase = ((size_t)dir * MTOT + (size_t)s_x * BATCH) * N3 + nblk * TN_S;
#pragma unroll
    for (int q = 0; q < 4; q++) {
        int p  = t * 4 + q;          // 2048 (b, jj) pairs
        int b  = p >> 4, jj = p & 15;
        int j  = nblk * 16 + jj;
        int c  = jj * 3;
        float ghr = sC[b * 49 + c];
        float ghz = sC[b * 49 + c + 1];
        float gnh = sC[b * 49 + c + 2] + g_bias[dir][3][j];
        const float* gip = g_gi + gibase + (size_t)b * N3 + c;
        float gr  = ghr + gip[0] + g_bias[dir][0][j];
        float gz  = ghz + gip[1] + g_bias[dir][1][j];
        float gni = gip[2] + g_bias[dir][2][j];
        float r = fsig(gr);
        float z = fsig(gz);
        float n = ftanh(gni + r * gnh);
        int   hidx = (dir * BATCH + b) * HDIM + j;
        float hold = g_h[hidx];
        float hnew = (1.f - z) * n + z * hold;
        g_h[hidx] = hnew;
        i8 hi, lo; q2(hnew, 127.f, hi, lo);
        int hb = ((wpar * 2 + dir) * BATCH + b) * HDIM + j;
        g_h8h[hb] = hi;
        g_h8l[hb] = lo;
        out[((size_t)step * BATCH + b) * (2 * HDIM) + dir * HDIM + j] = hnew;
    }
}

// ---------------- launch ----------------
extern "C" void kernel_launch(void* const* d_in, const int* in_sizes, int n_in,
                              void* d_out, int out_size) {
    const float* x     = (const float*)d_in[0];
    const float* Wih_f = (const float*)d_in[1];
    const float* Whh_f = (const float*)d_in[2];
    const float* bih_f = (const float*)d_in[3];
    const float* bhh_f = (const float*)d_in[4];
    const float* Wih_b = (const float*)d_in[5];
    const float* Whh_b = (const float*)d_in[6];
    const float* bih_b = (const float*)d_in[7];
    const float* bhh_b = (const float*)d_in[8];
    float* out = (float*)d_out;

    cudaFuncSetAttribute(gi_gemm,  cudaFuncAttributeMaxDynamicSharedMemorySize, SMEM_G);
    cudaFuncSetAttribute(gru_step, cudaFuncAttributeMaxDynamicSharedMemorySize, SMEM_S);

    zero_ax_kernel<<<1, 32>>>();
    absmax_x_kernel<<<1024, 256>>>(x);
    finalize_scales_kernel<<<1, 1>>>();
    pack_x_kernel<<<(int)((size_t)MTOT * IDIM / 256), 256>>>(x);
    pack_w_kernel<<<2 * N3 * 2048 / 256, 256>>>(Wih_f, Whh_f, Wih_b, Whh_b);
    pack_bias_kernel<<<8, 256>>>(bih_f, bhh_f, bih_b, bhh_b);
    init_h_kernel<<<1024, 256>>>();

    gi_gemm<<<dim3(NBLK_G, MTOT / 128, 2), 512, SMEM_G>>>();

    for (int s = 0; s < S_LEN; ++s)
        gru_step<<<dim3(NBLK_S, 2), 512, SMEM_S>>>(out, s);
}

// round 7
// speedup vs baseline: 2.2547x; 2.2547x over previous
#include <cuda_runtime.h>
#include <cuda_fp16.h>
#include <stdint.h>

typedef __half f16;

#define S_LEN 512
#define BATCH 128
#define IDIM  1024
#define HDIM  1024
#define KDIM  2048       // packed weights: k<1024 -> Wih, k>=1024 -> Whh
#define N3    3072       // 3 gates * H, interleaved col = 3*j + gate
#define KT    32         // K tile (f16 elems)
#define ASTR  40         // smem row stride (f16): conflict-free, 16B-aligned rows
#define NSTG  3
#define MTOT  (S_LEN*BATCH)

#define TN_S  48               // step-kernel N tile (2 ngrp x 24)
#define TN_G  96               // gi-kernel N tile   (2 ngrp x 48)
#define NBLK_S (N3/TN_S)       // 64
#define NBLK_G (N3/TN_G)       // 32

#define STAGE_S (2*128*ASTR + TN_S*ASTR)   // 12160 f16
#define STAGE_G (2*128*ASTR + TN_G*ASTR)   // 14080 f16
#define SMEM_S  (NSTG*STAGE_S*2)           // 72960 B
#define SMEM_G  (NSTG*STAGE_G*2)           // 84480 B

// ---------------- device scratch ----------------
__device__ f16   g_x_hi[(size_t)MTOT*IDIM];
__device__ f16   g_x_lo[(size_t)MTOT*IDIM];
__device__ f16   g_W[(size_t)2*N3*KDIM];     // single fp16 plane, [dir][n][k]
__device__ float g_bias[2][4][HDIM];         // br, bz, b_in, b_hn
__device__ float g_h[2*BATCH*HDIM];          // fp32 recurrent state
__device__ f16   g_hf_hi[2*2*BATCH*HDIM];    // [parity][dir][b][j]
__device__ f16   g_hf_lo[2*2*BATCH*HDIM];
__device__ float g_gi[(size_t)2*MTOT*N3];    // precomputed x@Wih^T

// ---------------- helpers ----------------
__device__ __forceinline__ void split2(float v, f16& hi, f16& lo) {
    hi = __float2half_rn(v);
    lo = __float2half_rn(v - __half2float(hi));
}

__device__ __forceinline__ void cp16(f16* dst, const f16* src) {
    unsigned d = (unsigned)__cvta_generic_to_shared(dst);
    asm volatile("cp.async.cg.shared.global [%0], [%1], 16;\n" :: "r"(d), "l"(src));
}

__device__ __forceinline__ uint32_t smaddr(const void* p) {
    return (uint32_t)__cvta_generic_to_shared(p);
}

__device__ __forceinline__ void ldsm_x4(uint32_t r[4], uint32_t a) {
    asm volatile("ldmatrix.sync.aligned.m8n8.x4.shared.b16 {%0,%1,%2,%3},[%4];"
                 : "=r"(r[0]), "=r"(r[1]), "=r"(r[2]), "=r"(r[3]) : "r"(a));
}

__device__ __forceinline__ void mma16816(float c[4], const uint32_t a[4],
                                         uint32_t b0, uint32_t b1) {
    asm volatile(
        "mma.sync.aligned.m16n8k16.row.col.f32.f16.f16.f32 "
        "{%0,%1,%2,%3},{%4,%5,%6,%7},{%8,%9},{%0,%1,%2,%3};"
        : "+f"(c[0]), "+f"(c[1]), "+f"(c[2]), "+f"(c[3])
        : "r"(a[0]), "r"(a[1]), "r"(a[2]), "r"(a[3]), "r"(b0), "r"(b1));
}

__device__ __forceinline__ float fsig(float x) {
    return __fdividef(1.f, 1.f + __expf(-x));
}
__device__ __forceinline__ float ftanh(float x) {
    return 1.f - __fdividef(2.f, __expf(2.f * x) + 1.f);
}

#define CP_COMMIT() asm volatile("cp.async.commit_group;")

// ---------------- prep kernels ----------------
__global__ void pack_x_kernel(const float* __restrict__ x) {
    int i = blockIdx.x * 256 + threadIdx.x;
    f16 hi, lo; split2(x[i], hi, lo);
    g_x_hi[i] = hi; g_x_lo[i] = lo;
}

__global__ void pack_w_kernel(const float* __restrict__ Wih_f, const float* __restrict__ Whh_f,
                              const float* __restrict__ Wih_b, const float* __restrict__ Whh_b) {
    int idx = blockIdx.x * 256 + threadIdx.x;
    int k   = idx % KDIM;
    int n   = (idx / KDIM) % N3;
    int dir = idx / (KDIM * N3);
    int j = n / 3, g = n % 3;
    int srow = g * HDIM + j;
    const float* Wih = dir ? Wih_b : Wih_f;
    const float* Whh = dir ? Whh_b : Whh_f;
    float v = (k < IDIM) ? Wih[srow * IDIM + k] : Whh[srow * HDIM + (k - IDIM)];
    g_W[idx] = __float2half_rn(v);
}

__global__ void pack_bias_kernel(const float* __restrict__ bih_f, const float* __restrict__ bhh_f,
                                 const float* __restrict__ bih_b, const float* __restrict__ bhh_b) {
    int i = blockIdx.x * 256 + threadIdx.x;   // 0..2047
    int dir = i >> 10, j = i & 1023;
    const float* bih = dir ? bih_b : bih_f;
    const float* bhh = dir ? bhh_b : bhh_f;
    g_bias[dir][0][j] = bih[j] + bhh[j];
    g_bias[dir][1][j] = bih[HDIM + j] + bhh[HDIM + j];
    g_bias[dir][2][j] = bih[2 * HDIM + j];
    g_bias[dir][3][j] = bhh[2 * HDIM + j];
}

__global__ void init_h_kernel() {
    int i = blockIdx.x * 256 + threadIdx.x;   // 2*2*B*H
    if (i < 2 * BATCH * HDIM) g_h[i] = 0.f;
    f16 z = __float2half_rn(0.f);
    g_hf_hi[i] = z; g_hf_lo[i] = z;
}

// ---------------- mainloop compute: warp = 16 rows x (NT*8) cols ----------------
// A split hi/lo (2 planes), B single plane. acc = (a_hi + a_lo) @ b^T exactly.
template<int NT>
__device__ __forceinline__ void compute_tile(f16* stage, int mwarp, int ngrp,
                                             int lane, float acc[NT][4]) {
    f16* pAh = stage;
    f16* pAl = stage + 128 * ASTR;
    f16* pB  = stage + 2 * 128 * ASTR;
    const uint32_t aoff = smaddr(pAh + (mwarp * 16 + (lane & 15)) * ASTR + (lane >> 4) * 8);
    const uint32_t aoffl = aoff + 128 * ASTR * 2;   // bytes: lo plane
    // B x4: 4 mats = rows (nt*8 + lane&7), col block (lane>>3)*8 -> covers k 0..31
    const uint32_t boff = smaddr(pB + (ngrp * (NT * 8) + (lane & 7)) * ASTR + (lane >> 3) * 8);

    uint32_t ah0[4], ah1[4], al0[4], al1[4];
    ldsm_x4(ah0, aoff);
    ldsm_x4(ah1, aoff + 16 * 2);        // ks=1: +16 f16 cols = 32 B
    ldsm_x4(al0, aoffl);
    ldsm_x4(al1, aoffl + 16 * 2);
#pragma unroll
    for (int nt = 0; nt < NT; ++nt) {
        uint32_t b4[4];                  // b4[0..1]: ks=0, b4[2..3]: ks=1
        ldsm_x4(b4, boff + nt * 8 * ASTR * 2);
        mma16816(acc[nt], ah0, b4[0], b4[1]);
        mma16816(acc[nt], al0, b4[0], b4[1]);
        mma16816(acc[nt], ah1, b4[2], b4[3]);
        mma16816(acc[nt], al1, b4[2], b4[3]);
    }
}

// ---------------- pre-GEMM: gi = x @ Wih^T for all steps ----------------
// grid: (NBLK_G=32, MTOT/128=512, 2), block 512 (16 warps: 8 M x 2 N)
__global__ void __launch_bounds__(512) gi_gemm() {
    extern __shared__ char smraw[];
    f16* sm = (f16*)smraw;

    const int nblk = blockIdx.x, mblk = blockIdx.y, dir = blockIdx.z;
    const int t = threadIdx.x, warp = t >> 5, lane = t & 31;
    const int mwarp = warp & 7, ngrp = warp >> 3;
    const int grp = lane >> 2, tq = lane & 3;

    auto stage = [&](int s) { return sm + s * STAGE_G; };

    auto copy_tile = [&](int kt, int buf) {
        f16* st = stage(buf);
        const int k0 = kt * KT;
        {
            int row = t >> 2;                 // 512 threads = 128 rows x 4 quads
            int kq  = (t & 3) * 8;
            size_t off = ((size_t)mblk * 128 + row) * IDIM + k0 + kq;
            cp16(st + row * ASTR + kq, g_x_hi + off);
            cp16(st + 128 * ASTR + row * ASTR + kq, g_x_lo + off);
        }
        if (t < 4 * TN_G) {                   // 384 slots
            int nloc = t >> 2;
            int kq   = (t & 3) * 8;
            size_t off = ((size_t)(dir * N3 + nblk * TN_G + nloc)) * KDIM + k0 + kq;
            cp16(st + 2 * 128 * ASTR + nloc * ASTR + kq, g_W + off);
        }
    };

    float acc[6][4];
#pragma unroll
    for (int i = 0; i < 6; i++)
#pragma unroll
        for (int q = 0; q < 4; q++) acc[i][q] = 0.f;

    copy_tile(0, 0); CP_COMMIT();
    copy_tile(1, 1); CP_COMMIT();

    const int NKT = IDIM / KT;   // 32
#pragma unroll 1
    for (int kt = 0; kt < NKT; ++kt) {
        if (kt < NKT - 1) asm volatile("cp.async.wait_group 1;");
        else              asm volatile("cp.async.wait_group 0;");
        __syncthreads();
        if (kt + 2 < NKT) { copy_tile(kt + 2, (kt + 2) % NSTG); CP_COMMIT(); }
        compute_tile<6>(stage(kt % NSTG), mwarp, ngrp, lane, acc);
    }

    // epilogue: write fragments straight to g_gi
    const int m = mblk * 128 + mwarp * 16 + grp;
    const int colbase = nblk * TN_G + ngrp * 48 + tq * 2;
    float* d0 = g_gi + ((size_t)dir * MTOT + m) * N3;
    float* d1 = d0 + (size_t)8 * N3;
#pragma unroll
    for (int nt = 0; nt < 6; ++nt) {
        int col = colbase + nt * 8;
        d0[col]     = acc[nt][0];
        d0[col + 1] = acc[nt][1];
        d1[col]     = acc[nt][2];
        d1[col + 1] = acc[nt][3];
    }
}

// ---------------- recurrent step: gh = h @ Whh^T, then gates ----------------
// grid: (NBLK_S=64, 2), block 512 (16 warps: 8 M x 2 N)
__global__ void __launch_bounds__(512) gru_step(float* __restrict__ out, int step) {
    extern __shared__ char smraw[];
    f16* sm = (f16*)smraw;

    const int nblk = blockIdx.x, dir = blockIdx.y;
    const int t = threadIdx.x, warp = t >> 5, lane = t & 31;
    const int mwarp = warp & 7, ngrp = warp >> 3;
    const int grp = lane >> 2, tq = lane & 3;
    const int rpar = step & 1, wpar = rpar ^ 1;
    const int s_x  = dir ? (S_LEN - 1 - step) : step;

    auto stage = [&](int s) { return sm + s * STAGE_S; };

    auto copy_tile = [&](int kt, int buf) {
        f16* st = stage(buf);
        const int k0 = kt * KT;
        {
            int row = t >> 2;
            int kq  = (t & 3) * 8;
            int off = ((rpar * 2 + dir) * BATCH + row) * HDIM + k0 + kq;
            cp16(st + row * ASTR + kq, g_hf_hi + off);
            cp16(st + 128 * ASTR + row * ASTR + kq, g_hf_lo + off);
        }
        if (t < 4 * TN_S) {
            int nloc = t >> 2;
            int kq   = (t & 3) * 8;
            size_t off = ((size_t)(dir * N3 + nblk * TN_S + nloc)) * KDIM + IDIM + k0 + kq;
            cp16(st + 2 * 128 * ASTR + nloc * ASTR + kq, g_W + off);
        }
    };

    float acc[3][4];
#pragma unroll
    for (int i = 0; i < 3; i++)
#pragma unroll
        for (int q = 0; q < 4; q++) acc[i][q] = 0.f;

    copy_tile(0, 0); CP_COMMIT();
    copy_tile(1, 1); CP_COMMIT();

    const int NKT = HDIM / KT;   // 32
#pragma unroll 1
    for (int kt = 0; kt < NKT; ++kt) {
        if (kt < NKT - 1) asm volatile("cp.async.wait_group 1;");
        else              asm volatile("cp.async.wait_group 0;");
        __syncthreads();
        if (kt + 2 < NKT) { copy_tile(kt + 2, (kt + 2) % NSTG); CP_COMMIT(); }
        compute_tile<3>(stage(kt % NSTG), mwarp, ngrp, lane, acc);
    }

    // ---- epilogue: accumulators -> smem, then GRU gates ----
    __syncthreads();
    float* sC = (float*)smraw;   // [128][49]
    {
        const int row  = mwarp * 16 + grp;
        const int colb = ngrp * 24 + tq * 2;
#pragma unroll
        for (int nt = 0; nt < 3; ++nt) {
            int col = colb + nt * 8;
            sC[row * 49 + col]           = acc[nt][0];
            sC[row * 49 + col + 1]       = acc[nt][1];
            sC[(row + 8) * 49 + col]     = acc[nt][2];
            sC[(row + 8) * 49 + col + 1] = acc[nt][3];
        }
    }
    __syncthreads();

    const size_t gibase = ((size_t)dir * MTOT + (size_t)s_x * BATCH) * N3 + nblk * TN_S;
#pragma unroll
    for (int q = 0; q < 4; q++) {
        int p  = t * 4 + q;          // 2048 (b, jj) pairs
        int b  = p >> 4, jj = p & 15;
        int j  = nblk * 16 + jj;
        int c  = jj * 3;
        float ghr = sC[b * 49 + c];
        float ghz = sC[b * 49 + c + 1];
        float gnh = sC[b * 49 + c + 2] + g_bias[dir][3][j];
        const float* gip = g_gi + gibase + (size_t)b * N3 + c;
        float gr  = ghr + gip[0] + g_bias[dir][0][j];
        float gz  = ghz + gip[1] + g_bias[dir][1][j];
        float gni = gip[2] + g_bias[dir][2][j];
        float r = fsig(gr);
        float z = fsig(gz);
        float n = ftanh(gni + r * gnh);
        int   hidx = (dir * BATCH + b) * HDIM + j;
        float hold = g_h[hidx];
        float hnew = (1.f - z) * n + z * hold;
        g_h[hidx] = hnew;
        f16 hi, lo; split2(hnew, hi, lo);
        int hb = ((wpar * 2 + dir) * BATCH + b) * HDIM + j;
        g_hf_hi[hb] = hi;
        g_hf_lo[hb] = lo;
        out[((size_t)step * BATCH + b) * (2 * HDIM) + dir * HDIM + j] = hnew;
    }
}

// ---------------- launch ----------------
extern "C" void kernel_launch(void* const* d_in, const int* in_sizes, int n_in,
                              void* d_out, int out_size) {
    const float* x     = (const float*)d_in[0];
    const float* Wih_f = (const float*)d_in[1];
    const float* Whh_f = (const float*)d_in[2];
    const float* bih_f = (const float*)d_in[3];
    const float* bhh_f = (const float*)d_in[4];
    const float* Wih_b = (const float*)d_in[5];
    const float* Whh_b = (const float*)d_in[6];
    const float* bih_b = (const float*)d_in[7];
    const float* bhh_b = (const float*)d_in[8];
    float* out = (float*)d_out;

    cudaFuncSetAttribute(gi_gemm,  cudaFuncAttributeMaxDynamicSharedMemorySize, SMEM_G);
    cudaFuncSetAttribute(gru_step, cudaFuncAttributeMaxDynamicSharedMemorySize, SMEM_S);

    pack_x_kernel<<<(int)((size_t)MTOT * IDIM / 256), 256>>>(x);
    pack_w_kernel<<<2 * N3 * KDIM / 256, 256>>>(Wih_f, Whh_f, Wih_b, Whh_b);
    pack_bias_kernel<<<8, 256>>>(bih_f, bhh_f, bih_b, bhh_b);
    init_h_kernel<<<2 * 2 * BATCH * HDIM / 256, 256>>>();

    gi_gemm<<<dim3(NBLK_G, MTOT / 128, 2), 512, SMEM_G>>>();

    for (int s = 0; s < S_LEN; ++s)
        gru_step<<<dim3(NBLK_S, 2), 512, SMEM_S>>>(out, s);
}

// round 8
// speedup vs baseline: 3.2067x; 1.4223x over previous
#include <cuda_runtime.h>
#include <cuda_fp16.h>
#include <stdint.h>

typedef __half f16;

#define S_LEN 512
#define BATCH 128
#define IDIM  1024
#define HDIM  1024
#define KDIM  2048       // packed weights: k<1024 -> Wih, k>=1024 -> Whh
#define N3    3072       // 3 gates * H, interleaved col = 3*j + gate
#define KT    32         // K tile (f16 elems)
#define ASTR  40         // smem row stride (f16): conflict-free, 16B-aligned rows
#define NSTG  3
#define MTOT  (S_LEN*BATCH)

#define TN_S  48               // step-kernel N tile (2 ngrp x 24)
#define TN_G  96               // gi-kernel N tile   (2 ngrp x 48)
#define NBLK_S (N3/TN_S)       // 64
#define NBLK_G (N3/TN_G)       // 32

#define STAGE_S ((128 + TN_S)*ASTR)        // 7040 f16
#define STAGE_G ((128 + TN_G)*ASTR)        // 8960 f16
#define SMEM_S  (NSTG*STAGE_S*2)           // 42240 B
#define SMEM_G  (NSTG*STAGE_G*2)           // 53760 B

// ---------------- device scratch ----------------
__device__ f16   g_x[(size_t)MTOT*IDIM];
__device__ f16   g_W[(size_t)2*N3*KDIM];     // single fp16 plane, [dir][n][k]
__device__ float g_bias[2][4][HDIM];         // br, bz, b_in, b_hn
__device__ float g_h[2*BATCH*HDIM];          // fp32 recurrent state
__device__ f16   g_hf[2*2*BATCH*HDIM];       // [parity][dir][b][j]
__device__ float g_gi[(size_t)2*MTOT*N3];    // precomputed x@Wih^T

// ---------------- helpers ----------------
__device__ __forceinline__ void cp16(f16* dst, const f16* src) {
    unsigned d = (unsigned)__cvta_generic_to_shared(dst);
    asm volatile("cp.async.cg.shared.global [%0], [%1], 16;\n" :: "r"(d), "l"(src));
}

__device__ __forceinline__ uint32_t smaddr(const void* p) {
    return (uint32_t)__cvta_generic_to_shared(p);
}

__device__ __forceinline__ void ldsm_x4(uint32_t r[4], uint32_t a) {
    asm volatile("ldmatrix.sync.aligned.m8n8.x4.shared.b16 {%0,%1,%2,%3},[%4];"
                 : "=r"(r[0]), "=r"(r[1]), "=r"(r[2]), "=r"(r[3]) : "r"(a));
}

__device__ __forceinline__ void mma16816(float c[4], const uint32_t a[4],
                                         uint32_t b0, uint32_t b1) {
    asm volatile(
        "mma.sync.aligned.m16n8k16.row.col.f32.f16.f16.f32 "
        "{%0,%1,%2,%3},{%4,%5,%6,%7},{%8,%9},{%0,%1,%2,%3};"
        : "+f"(c[0]), "+f"(c[1]), "+f"(c[2]), "+f"(c[3])
        : "r"(a[0]), "r"(a[1]), "r"(a[2]), "r"(a[3]), "r"(b0), "r"(b1));
}

__device__ __forceinline__ float fsig(float x) {
    return __fdividef(1.f, 1.f + __expf(-x));
}
__device__ __forceinline__ float ftanh(float x) {
    return 1.f - __fdividef(2.f, __expf(2.f * x) + 1.f);
}

#define CP_COMMIT() asm volatile("cp.async.commit_group;")

// ---------------- prep kernels ----------------
__global__ void pack_x_kernel(const float* __restrict__ x) {
    int i = blockIdx.x * 256 + threadIdx.x;
    g_x[i] = __float2half_rn(x[i]);
}

__global__ void pack_w_kernel(const float* __restrict__ Wih_f, const float* __restrict__ Whh_f,
                              const float* __restrict__ Wih_b, const float* __restrict__ Whh_b) {
    int idx = blockIdx.x * 256 + threadIdx.x;
    int k   = idx % KDIM;
    int n   = (idx / KDIM) % N3;
    int dir = idx / (KDIM * N3);
    int j = n / 3, g = n % 3;
    int srow = g * HDIM + j;
    const float* Wih = dir ? Wih_b : Wih_f;
    const float* Whh = dir ? Whh_b : Whh_f;
    float v = (k < IDIM) ? Wih[srow * IDIM + k] : Whh[srow * HDIM + (k - IDIM)];
    g_W[idx] = __float2half_rn(v);
}

__global__ void pack_bias_kernel(const float* __restrict__ bih_f, const float* __restrict__ bhh_f,
                                 const float* __restrict__ bih_b, const float* __restrict__ bhh_b) {
    int i = blockIdx.x * 256 + threadIdx.x;   // 0..2047
    int dir = i >> 10, j = i & 1023;
    const float* bih = dir ? bih_b : bih_f;
    const float* bhh = dir ? bhh_b : bhh_f;
    g_bias[dir][0][j] = bih[j] + bhh[j];
    g_bias[dir][1][j] = bih[HDIM + j] + bhh[HDIM + j];
    g_bias[dir][2][j] = bih[2 * HDIM + j];
    g_bias[dir][3][j] = bhh[2 * HDIM + j];
}

__global__ void init_h_kernel() {
    int i = blockIdx.x * 256 + threadIdx.x;   // 2*2*B*H
    if (i < 2 * BATCH * HDIM) g_h[i] = 0.f;
    g_hf[i] = __float2half_rn(0.f);
}

// ---------------- mainloop compute: warp = 16 rows x (NT*8) cols, 1-term fp16 ----------------
template<int NT>
__device__ __forceinline__ void compute_tile(f16* stage, int mwarp, int ngrp,
                                             int lane, float acc[NT][4]) {
    f16* pA = stage;
    f16* pB = stage + 128 * ASTR;
    const uint32_t aoff = smaddr(pA + (mwarp * 16 + (lane & 15)) * ASTR + (lane >> 4) * 8);
    // B x4: rows (nt*8 + lane&7), col block (lane>>3)*8 -> covers k 0..31
    const uint32_t boff = smaddr(pB + (ngrp * (NT * 8) + (lane & 7)) * ASTR + (lane >> 3) * 8);

    uint32_t a0[4], a1[4];
    ldsm_x4(a0, aoff);
    ldsm_x4(a1, aoff + 16 * 2);          // ks=1: +16 f16 cols = 32 B
#pragma unroll
    for (int nt = 0; nt < NT; ++nt) {
        uint32_t b4[4];                  // b4[0..1]: ks=0, b4[2..3]: ks=1
        ldsm_x4(b4, boff + nt * 8 * ASTR * 2);
        mma16816(acc[nt], a0, b4[0], b4[1]);
        mma16816(acc[nt], a1, b4[2], b4[3]);
    }
}

// ---------------- pre-GEMM: gi = x @ Wih^T for all steps ----------------
// grid: (NBLK_G=32, MTOT/128=512, 2), block 512 (16 warps: 8 M x 2 N)
__global__ void __launch_bounds__(512) gi_gemm() {
    extern __shared__ char smraw[];
    f16* sm = (f16*)smraw;

    const int nblk = blockIdx.x, mblk = blockIdx.y, dir = blockIdx.z;
    const int t = threadIdx.x, warp = t >> 5, lane = t & 31;
    const int mwarp = warp & 7, ngrp = warp >> 3;
    const int grp = lane >> 2, tq = lane & 3;

    auto stage = [&](int s) { return sm + s * STAGE_G; };

    auto copy_tile = [&](int kt, int buf) {
        f16* st = stage(buf);
        const int k0 = kt * KT;
        {
            int row = t >> 2;                 // 512 threads = 128 rows x 4 quads
            int kq  = (t & 3) * 8;
            size_t off = ((size_t)mblk * 128 + row) * IDIM + k0 + kq;
            cp16(st + row * ASTR + kq, g_x + off);
        }
        if (t < 4 * TN_G) {                   // 384 slots
            int nloc = t >> 2;
            int kq   = (t & 3) * 8;
            size_t off = ((size_t)(dir * N3 + nblk * TN_G + nloc)) * KDIM + k0 + kq;
            cp16(st + 128 * ASTR + nloc * ASTR + kq, g_W + off);
        }
    };

    float acc[6][4];
#pragma unroll
    for (int i = 0; i < 6; i++)
#pragma unroll
        for (int q = 0; q < 4; q++) acc[i][q] = 0.f;

    copy_tile(0, 0); CP_COMMIT();
    copy_tile(1, 1); CP_COMMIT();

    const int NKT = IDIM / KT;   // 32
#pragma unroll 1
    for (int kt = 0; kt < NKT; ++kt) {
        if (kt < NKT - 1) asm volatile("cp.async.wait_group 1;");
        else              asm volatile("cp.async.wait_group 0;");
        __syncthreads();
        if (kt + 2 < NKT) { copy_tile(kt + 2, (kt + 2) % NSTG); CP_COMMIT(); }
        compute_tile<6>(stage(kt % NSTG), mwarp, ngrp, lane, acc);
    }

    // epilogue: write fragments straight to g_gi
    const int m = mblk * 128 + mwarp * 16 + grp;
    const int colbase = nblk * TN_G + ngrp * 48 + tq * 2;
    float* d0 = g_gi + ((size_t)dir * MTOT + m) * N3;
    float* d1 = d0 + (size_t)8 * N3;
#pragma unroll
    for (int nt = 0; nt < 6; ++nt) {
        int col = colbase + nt * 8;
        d0[col]     = acc[nt][0];
        d0[col + 1] = acc[nt][1];
        d1[col]     = acc[nt][2];
        d1[col + 1] = acc[nt][3];
    }
}

// ---------------- recurrent step: gh = h @ Whh^T, then gates ----------------
// grid: (NBLK_S=64, 2), block 512 (16 warps: 8 M x 2 N)
__global__ void __launch_bounds__(512) gru_step(float* __restrict__ out, int step) {
    extern __shared__ char smraw[];
    f16* sm = (f16*)smraw;

    const int nblk = blockIdx.x, dir = blockIdx.y;
    const int t = threadIdx.x, warp = t >> 5, lane = t & 31;
    const int mwarp = warp & 7, ngrp = warp >> 3;
    const int grp = lane >> 2, tq = lane & 3;
    const int rpar = step & 1, wpar = rpar ^ 1;
    const int s_x  = dir ? (S_LEN - 1 - step) : step;

    auto stage = [&](int s) { return sm + s * STAGE_S; };

    auto copy_tile = [&](int kt, int buf) {
        f16* st = stage(buf);
        const int k0 = kt * KT;
        {
            int row = t >> 2;
            int kq  = (t & 3) * 8;
            int off = ((rpar * 2 + dir) * BATCH + row) * HDIM + k0 + kq;
            cp16(st + row * ASTR + kq, g_hf + off);
        }
        if (t < 4 * TN_S) {
            int nloc = t >> 2;
            int kq   = (t & 3) * 8;
            size_t off = ((size_t)(dir * N3 + nblk * TN_S + nloc)) * KDIM + IDIM + k0 + kq;
            cp16(st + 128 * ASTR + nloc * ASTR + kq, g_W + off);
        }
    };

    float acc[3][4];
#pragma unroll
    for (int i = 0; i < 3; i++)
#pragma unroll
        for (int q = 0; q < 4; q++) acc[i][q] = 0.f;

    copy_tile(0, 0); CP_COMMIT();
    copy_tile(1, 1); CP_COMMIT();

    const int NKT = HDIM / KT;   // 32
#pragma unroll 1
    for (int kt = 0; kt < NKT; ++kt) {
        if (kt < NKT - 1) asm volatile("cp.async.wait_group 1;");
        else              asm volatile("cp.async.wait_group 0;");
        __syncthreads();
        if (kt + 2 < NKT) { copy_tile(kt + 2, (kt + 2) % NSTG); CP_COMMIT(); }
        compute_tile<3>(stage(kt % NSTG), mwarp, ngrp, lane, acc);
    }

    // ---- epilogue: accumulators -> smem, then GRU gates ----
    __syncthreads();
    float* sC = (float*)smraw;   // [128][49]
    {
        const int row  = mwarp * 16 + grp;
        const int colb = ngrp * 24 + tq * 2;
#pragma unroll
        for (int nt = 0; nt < 3; ++nt) {
            int col = colb + nt * 8;
            sC[row * 49 + col]           = acc[nt][0];
            sC[row * 49 + col + 1]       = acc[nt][1];
            sC[(row + 8) * 49 + col]     = acc[nt][2];
            sC[(row + 8) * 49 + col + 1] = acc[nt][3];
        }
    }
    __syncthreads();

    const size_t gibase = ((size_t)dir * MTOT + (size_t)s_x * BATCH) * N3 + nblk * TN_S;
#pragma unroll
    for (int q = 0; q < 4; q++) {
        int p  = t * 4 + q;          // 2048 (b, jj) pairs
        int b  = p >> 4, jj = p & 15;
        int j  = nblk * 16 + jj;
        int c  = jj * 3;
        float ghr = sC[b * 49 + c];
        float ghz = sC[b * 49 + c + 1];
        float gnh = sC[b * 49 + c + 2] + g_bias[dir][3][j];
        const float* gip = g_gi + gibase + (size_t)b * N3 + c;
        float gr  = ghr + gip[0] + g_bias[dir][0][j];
        float gz  = ghz + gip[1] + g_bias[dir][1][j];
        float gni = gip[2] + g_bias[dir][2][j];
        float r = fsig(gr);
        float z = fsig(gz);
        float n = ftanh(gni + r * gnh);
        int   hidx = (dir * BATCH + b) * HDIM + j;
        float hold = g_h[hidx];
        float hnew = (1.f - z) * n + z * hold;
        g_h[hidx] = hnew;
        int hb = ((wpar * 2 + dir) * BATCH + b) * HDIM + j;
        g_hf[hb] = __float2half_rn(hnew);
        out[((size_t)step * BATCH + b) * (2 * HDIM) + dir * HDIM + j] = hnew;
    }
}

// ---------------- launch ----------------
extern "C" void kernel_launch(void* const* d_in, const int* in_sizes, int n_in,
                              void* d_out, int out_size) {
    const float* x     = (const float*)d_in[0];
    const float* Wih_f = (const float*)d_in[1];
    const float* Whh_f = (const float*)d_in[2];
    const float* bih_f = (const float*)d_in[3];
    const float* bhh_f = (const float*)d_in[4];
    const float* Wih_b = (const float*)d_in[5];
    const float* Whh_b = (const float*)d_in[6];
    const float* bih_b = (const float*)d_in[7];
    const float* bhh_b = (const float*)d_in[8];
    float* out = (float*)d_out;

    cudaFuncSetAttribute(gi_gemm,  cudaFuncAttributeMaxDynamicSharedMemorySize, SMEM_G);
    cudaFuncSetAttribute(gru_step, cudaFuncAttributeMaxDynamicSharedMemorySize, SMEM_S);

    pack_x_kernel<<<(int)((size_t)MTOT * IDIM / 256), 256>>>(x);
    pack_w_kernel<<<2 * N3 * KDIM / 256, 256>>>(Wih_f, Whh_f, Wih_b, Whh_b);
    pack_bias_kernel<<<8, 256>>>(bih_f, bhh_f, bih_b, bhh_b);
    init_h_kernel<<<2 * 2 * BATCH * HDIM / 256, 256>>>();

    gi_gemm<<<dim3(NBLK_G, MTOT / 128, 2), 512, SMEM_G>>>();

    for (int s = 0; s < S_LEN; ++s)
        gru_step<<<dim3(NBLK_S, 2), 512, SMEM_S>>>(out, s);
}

// round 9
// speedup vs baseline: 3.5677x; 1.1126x over previous
#include <cuda_runtime.h>
#include <cuda_fp16.h>
#include <stdint.h>

typedef __half f16;

#define S_LEN 512
#define BATCH 128
#define IDIM  1024
#define HDIM  1024
#define KDIM  2048       // packed weights: k<1024 -> Wih, k>=1024 -> Whh
#define N3    3072       // 3 gates * H, interleaved col = 3*j + gate
#define KT    32         // K tile (f16 elems)
#define ASTR  40         // smem row stride (f16)
#define NSTG  3
#define MTOT  (S_LEN*BATCH)

#define TN_S  48               // step N tile (2 ngrp x 24)
#define TN_G  96               // gi N tile   (2 ngrp x 48)
#define NBLK_S (N3/TN_S)       // 64
#define NBLK_G (N3/TN_G)       // 32
#define NBLOCKS (NBLK_S*2)     // 128 persistent CTAs

#define STAGE_G ((128 + TN_G)*ASTR)        // 8960 f16
#define SMEM_G  (NSTG*STAGE_G*2)           // 53760 B

// persistent kernel smem: 3 A stages + resident W
#define APLANE   (128*ASTR)                    // f16 per A stage = 5120
#define W_OFF    (NSTG*APLANE)                 // 15360 f16
#define W_CH     (TN_S*ASTR)                   // 1920 f16 per k-chunk
#define NKT_S    (HDIM/KT)                     // 32
#define SMEM_P   ((W_OFF + NKT_S*W_CH)*2)      // 153600 B

// ---------------- device scratch ----------------
__device__ f16   g_x[(size_t)MTOT*IDIM];
__device__ f16   g_W[(size_t)2*N3*KDIM];     // [dir][n][k] fp16
__device__ float g_bias[2][4][HDIM];         // br, bz, b_in, b_hn
__device__ f16   g_hf[2*2*BATCH*HDIM];       // [parity][dir][b][j]
__device__ float g_gi[(size_t)2*MTOT*N3];    // precomputed x@Wih^T
__device__ unsigned g_bar;

// ---------------- helpers ----------------
__device__ __forceinline__ void cp16(f16* dst, const f16* src) {
    unsigned d = (unsigned)__cvta_generic_to_shared(dst);
    asm volatile("cp.async.cg.shared.global [%0], [%1], 16;\n" :: "r"(d), "l"(src));
}
__device__ __forceinline__ uint32_t smaddr(const void* p) {
    return (uint32_t)__cvta_generic_to_shared(p);
}
__device__ __forceinline__ void ldsm_x4(uint32_t r[4], uint32_t a) {
    asm volatile("ldmatrix.sync.aligned.m8n8.x4.shared.b16 {%0,%1,%2,%3},[%4];"
                 : "=r"(r[0]), "=r"(r[1]), "=r"(r[2]), "=r"(r[3]) : "r"(a));
}
__device__ __forceinline__ void mma16816(float c[4], const uint32_t a[4],
                                         uint32_t b0, uint32_t b1) {
    asm volatile(
        "mma.sync.aligned.m16n8k16.row.col.f32.f16.f16.f32 "
        "{%0,%1,%2,%3},{%4,%5,%6,%7},{%8,%9},{%0,%1,%2,%3};"
        : "+f"(c[0]), "+f"(c[1]), "+f"(c[2]), "+f"(c[3])
        : "r"(a[0]), "r"(a[1]), "r"(a[2]), "r"(a[3]), "r"(b0), "r"(b1));
}
__device__ __forceinline__ float fsig(float x) {
    return __fdividef(1.f, 1.f + __expf(-x));
}
__device__ __forceinline__ float ftanh(float x) {
    return 1.f - __fdividef(2.f, __expf(2.f * x) + 1.f);
}

#define CP_COMMIT() asm volatile("cp.async.commit_group;")

// ---------------- prep kernels ----------------
__global__ void pack_x_kernel(const float* __restrict__ x) {
    int i = blockIdx.x * 256 + threadIdx.x;
    g_x[i] = __float2half_rn(x[i]);
}

__global__ void pack_w_kernel(const float* __restrict__ Wih_f, const float* __restrict__ Whh_f,
                              const float* __restrict__ Wih_b, const float* __restrict__ Whh_b) {
    int idx = blockIdx.x * 256 + threadIdx.x;
    int k   = idx % KDIM;
    int n   = (idx / KDIM) % N3;
    int dir = idx / (KDIM * N3);
    int j = n / 3, g = n % 3;
    int srow = g * HDIM + j;
    const float* Wih = dir ? Wih_b : Wih_f;
    const float* Whh = dir ? Whh_b : Whh_f;
    float v = (k < IDIM) ? Wih[srow * IDIM + k] : Whh[srow * HDIM + (k - IDIM)];
    g_W[idx] = __float2half_rn(v);
}

__global__ void pack_bias_kernel(const float* __restrict__ bih_f, const float* __restrict__ bhh_f,
                                 const float* __restrict__ bih_b, const float* __restrict__ bhh_b) {
    int i = blockIdx.x * 256 + threadIdx.x;   // 0..2047
    int dir = i >> 10, j = i & 1023;
    const float* bih = dir ? bih_b : bih_f;
    const float* bhh = dir ? bhh_b : bhh_f;
    g_bias[dir][0][j] = bih[j] + bhh[j];
    g_bias[dir][1][j] = bih[HDIM + j] + bhh[HDIM + j];
    g_bias[dir][2][j] = bih[2 * HDIM + j];
    g_bias[dir][3][j] = bhh[2 * HDIM + j];
}

__global__ void init_h_kernel() {
    int i = blockIdx.x * 256 + threadIdx.x;   // 2*2*B*H
    g_hf[i] = __float2half_rn(0.f);
    if (i == 0) g_bar = 0u;
}

// ---------------- gi GEMM (unchanged from R8) ----------------
template<int NT>
__device__ __forceinline__ void compute_tile(f16* pA, f16* pB, int mwarp, int ngrp,
                                             int lane, float acc[NT][4]) {
    const uint32_t aoff = smaddr(pA + (mwarp * 16 + (lane & 15)) * ASTR + (lane >> 4) * 8);
    const uint32_t boff = smaddr(pB + (ngrp * (NT * 8) + (lane & 7)) * ASTR + (lane >> 3) * 8);
    uint32_t a0[4], a1[4];
    ldsm_x4(a0, aoff);
    ldsm_x4(a1, aoff + 16 * 2);
#pragma unroll
    for (int nt = 0; nt < NT; ++nt) {
        uint32_t b4[4];
        ldsm_x4(b4, boff + nt * 8 * ASTR * 2);
        mma16816(acc[nt], a0, b4[0], b4[1]);
        mma16816(acc[nt], a1, b4[2], b4[3]);
    }
}

// grid: (NBLK_G=32, MTOT/128=512, 2), block 512 (16 warps: 8 M x 2 N)
__global__ void __launch_bounds__(512) gi_gemm() {
    extern __shared__ char smraw[];
    f16* sm = (f16*)smraw;

    const int nblk = blockIdx.x, mblk = blockIdx.y, dir = blockIdx.z;
    const int t = threadIdx.x, warp = t >> 5, lane = t & 31;
    const int mwarp = warp & 7, ngrp = warp >> 3;
    const int grp = lane >> 2, tq = lane & 3;

    auto stage = [&](int s) { return sm + s * STAGE_G; };

    auto copy_tile = [&](int kt, int buf) {
        f16* st = stage(buf);
        const int k0 = kt * KT;
        {
            int row = t >> 2;
            int kq  = (t & 3) * 8;
            size_t off = ((size_t)mblk * 128 + row) * IDIM + k0 + kq;
            cp16(st + row * ASTR + kq, g_x + off);
        }
        if (t < 4 * TN_G) {
            int nloc = t >> 2;
            int kq   = (t & 3) * 8;
            size_t off = ((size_t)(dir * N3 + nblk * TN_G + nloc)) * KDIM + k0 + kq;
            cp16(st + 128 * ASTR + nloc * ASTR + kq, g_W + off);
        }
    };

    float acc[6][4];
#pragma unroll
    for (int i = 0; i < 6; i++)
#pragma unroll
        for (int q = 0; q < 4; q++) acc[i][q] = 0.f;

    copy_tile(0, 0); CP_COMMIT();
    copy_tile(1, 1); CP_COMMIT();

    const int NKT = IDIM / KT;   // 32
#pragma unroll 1
    for (int kt = 0; kt < NKT; ++kt) {
        if (kt < NKT - 1) asm volatile("cp.async.wait_group 1;");
        else              asm volatile("cp.async.wait_group 0;");
        __syncthreads();
        if (kt + 2 < NKT) { copy_tile(kt + 2, (kt + 2) % NSTG); CP_COMMIT(); }
        compute_tile<6>(stage(kt % NSTG), stage(kt % NSTG) + 128 * ASTR, mwarp, ngrp, lane, acc);
    }

    const int m = mblk * 128 + mwarp * 16 + grp;
    const int colbase = nblk * TN_G + ngrp * 48 + tq * 2;
    float* d0 = g_gi + ((size_t)dir * MTOT + m) * N3;
    float* d1 = d0 + (size_t)8 * N3;
#pragma unroll
    for (int nt = 0; nt < 6; ++nt) {
        int col = colbase + nt * 8;
        d0[col]     = acc[nt][0];
        d0[col + 1] = acc[nt][1];
        d1[col]     = acc[nt][2];
        d1[col + 1] = acc[nt][3];
    }
}

// ---------------- persistent recurrent kernel ----------------
// grid: (NBLK_S=64, 2) = 128 CTAs, block 512 (16 warps: 8 M x 2 N).
// Whh tile resident in smem; h state + biases in registers; grid barrier per step.
__global__ void __launch_bounds__(512) gru_persist(float* __restrict__ out) {
    extern __shared__ char smraw[];
    f16* sm  = (f16*)smraw;
    f16* wsm = sm + W_OFF;

    const int nblk = blockIdx.x, dir = blockIdx.y;
    const int t = threadIdx.x, warp = t >> 5, lane = t & 31;
    const int mwarp = warp & 7, ngrp = warp >> 3;
    const int grp = lane >> 2, tq = lane & 3;

    // ---- preload Whh tile: 32 chunks x 48 rows x 32 k (ASTR-padded) ----
    for (int i = t; i < NKT_S * TN_S * 4; i += 512) {
        int kt   = i / (TN_S * 4);
        int r    = i % (TN_S * 4);
        int nloc = r >> 2, kq = (r & 3) * 8;
        size_t off = ((size_t)(dir * N3 + nblk * TN_S + nloc)) * KDIM + IDIM + kt * KT + kq;
        cp16(wsm + kt * W_CH + nloc * ASTR + kq, g_W + off);
    }
    CP_COMMIT();
    asm volatile("cp.async.wait_group 0;");
    __syncthreads();

    // ---- per-thread persistent state: 4 (b, jj) pairs ----
    float hreg[4];
    float bs0[4], bs1[4], bs2[4], bs3[4];
    int   jj_arr[4], b_arr[4];
#pragma unroll
    for (int q = 0; q < 4; q++) {
        int p = t * 4 + q;
        int b = p >> 4, jj = p & 15;
        int j = nblk * 16 + jj;
        b_arr[q] = b; jj_arr[q] = jj;
        hreg[q] = 0.f;
        bs0[q] = g_bias[dir][0][j];
        bs1[q] = g_bias[dir][1][j];
        bs2[q] = g_bias[dir][2][j];
        bs3[q] = g_bias[dir][3][j];
    }

    const unsigned nblocks = NBLK_S * 2;

#pragma unroll 1
    for (int step = 0; step < S_LEN; ++step) {
        const int rpar = step & 1, wpar = rpar ^ 1;
        const int s_x  = dir ? (S_LEN - 1 - step) : step;

        auto copyA = [&](int kt, int buf) {
            f16* st = sm + buf * APLANE;
            int row = t >> 2, kq = (t & 3) * 8;
            int off = ((rpar * 2 + dir) * BATCH + row) * HDIM + kt * KT + kq;
            cp16(st + row * ASTR + kq, g_hf + off);
        };

        float acc[3][4];
#pragma unroll
        for (int i = 0; i < 3; i++)
#pragma unroll
            for (int q = 0; q < 4; q++) acc[i][q] = 0.f;

        copyA(0, 0); CP_COMMIT();
        copyA(1, 1); CP_COMMIT();

#pragma unroll 1
        for (int kt = 0; kt < NKT_S; ++kt) {
            if (kt < NKT_S - 1) asm volatile("cp.async.wait_group 1;");
            else                asm volatile("cp.async.wait_group 0;");
            __syncthreads();
            if (kt + 2 < NKT_S) { copyA(kt + 2, (kt + 2) % NSTG); CP_COMMIT(); }
            compute_tile<3>(sm + (kt % NSTG) * APLANE, wsm + kt * W_CH, mwarp, ngrp, lane, acc);
        }

        // ---- epilogue: accumulators -> smem (overlays A stages), gates ----
        __syncthreads();
        float* sC = (float*)smraw;   // [128][49] = 25088 B < 3*APLANE*2
        {
            const int row  = mwarp * 16 + grp;
            const int colb = ngrp * 24 + tq * 2;
#pragma unroll
            for (int nt = 0; nt < 3; ++nt) {
                int col = colb + nt * 8;
                sC[row * 49 + col]           = acc[nt][0];
                sC[row * 49 + col + 1]       = acc[nt][1];
                sC[(row + 8) * 49 + col]     = acc[nt][2];
                sC[(row + 8) * 49 + col + 1] = acc[nt][3];
            }
        }
        __syncthreads();

        const float* gib = g_gi + ((size_t)dir * MTOT + (size_t)s_x * BATCH) * N3 + nblk * TN_S;
#pragma unroll
        for (int q = 0; q < 4; q++) {
            int b = b_arr[q], jj = jj_arr[q];
            int j = nblk * 16 + jj;
            int c = jj * 3;
            float ghr = sC[b * 49 + c];
            float ghz = sC[b * 49 + c + 1];
            float gnh = sC[b * 49 + c + 2] + bs3[q];
            const float* gip = gib + (size_t)b * N3 + c;
            float gr  = ghr + gip[0] + bs0[q];
            float gz  = ghz + gip[1] + bs1[q];
            float gni = gip[2] + bs2[q];
            float r = fsig(gr);
            float z = fsig(gz);
            float n = ftanh(gni + r * gnh);
            float hnew = (1.f - z) * n + z * hreg[q];
            hreg[q] = hnew;
            g_hf[((wpar * 2 + dir) * BATCH + b) * HDIM + j] = __float2half_rn(hnew);
            out[((size_t)step * BATCH + b) * (2 * HDIM) + dir * HDIM + j] = hnew;
        }

        // ---- grid barrier (all 128 CTAs resident) ----
        if (step < S_LEN - 1) {
            __syncthreads();
            if (t == 0) {
                __threadfence();
                atomicAdd(&g_bar, 1u);
                unsigned target = nblocks * (unsigned)(step + 1);
                while (*(volatile unsigned*)&g_bar < target) __nanosleep(64);
                __threadfence();
            }
            __syncthreads();
        }
    }
}

// ---------------- launch ----------------
extern "C" void kernel_launch(void* const* d_in, const int* in_sizes, int n_in,
                              void* d_out, int out_size) {
    const float* x     = (const float*)d_in[0];
    const float* Wih_f = (const float*)d_in[1];
    const float* Whh_f = (const float*)d_in[2];
    const float* bih_f = (const float*)d_in[3];
    const float* bhh_f = (const float*)d_in[4];
    const float* Wih_b = (const float*)d_in[5];
    const float* Whh_b = (const float*)d_in[6];
    const float* bih_b = (const float*)d_in[7];
    const float* bhh_b = (const float*)d_in[8];
    float* out = (float*)d_out;

    cudaFuncSetAttribute(gi_gemm,     cudaFuncAttributeMaxDynamicSharedMemorySize, SMEM_G);
    cudaFuncSetAttribute(gru_persist, cudaFuncAttributeMaxDynamicSharedMemorySize, SMEM_P);

    pack_x_kernel<<<(int)((size_t)MTOT * IDIM / 256), 256>>>(x);
    pack_w_kernel<<<2 * N3 * KDIM / 256, 256>>>(Wih_f, Whh_f, Wih_b, Whh_b);
    pack_bias_kernel<<<8, 256>>>(bih_f, bhh_f, bih_b, bhh_b);
    init_h_kernel<<<2 * 2 * BATCH * HDIM / 256, 256>>>();

    gi_gemm<<<dim3(NBLK_G, MTOT / 128, 2), 512, SMEM_G>>>();

    gru_persist<<<dim3(NBLK_S, 2), 512, SMEM_P>>>(out);
}

// round 10
// speedup vs baseline: 3.7469x; 1.0502x over previous
#include <cuda_runtime.h>
#include <cuda_fp16.h>
#include <stdint.h>

typedef __half f16;

#define S_LEN 512
#define BATCH 128
#define IDIM  1024
#define HDIM  1024
#define KDIM  2048       // packed weights: k<1024 -> Wih, k>=1024 -> Whh
#define N3    3072       // 3 gates * H, interleaved col = 3*j + gate
#define MTOT  (S_LEN*BATCH)

#define TN_S  48               // step N tile (2 ngrp x 24)
#define TN_G  96               // gi N tile   (2 ngrp x 48)
#define NBLK_S (N3/TN_S)       // 64
#define NBLK_G (N3/TN_G)       // 32

// ---- gi GEMM layout (unchanged, KT=32/ASTR=40) ----
#define KT    32
#define ASTR  40
#define NSTG  3
#define STAGE_G ((128 + TN_G)*ASTR)        // 8960 f16
#define SMEM_G  (NSTG*STAGE_G*2)           // 53760 B

// ---- persistent kernel layout (KT=64 / ASTR=72) ----
#define KTP    64
#define ASTRP  72
#define NKTP   (HDIM/KTP)                  // 16
#define APLANE (128*ASTRP)                 // 9216 f16 per A stage
#define W_OFF  (NSTG*APLANE)               // 27648 f16
#define W_CH   (TN_S*ASTRP)                // 3456 f16 per k-chunk
#define SMEM_P ((W_OFF + NKTP*W_CH)*2)     // 165888 B

// ---------------- device scratch ----------------
__device__ f16   g_x[(size_t)MTOT*IDIM];
__device__ f16   g_W[(size_t)2*N3*KDIM];     // [dir][n][k] fp16
__device__ float g_bias[2][4][HDIM];         // br, bz, b_in, b_hn
__device__ f16   g_hf[2*2*BATCH*HDIM];       // [parity][dir][b][j]
__device__ float g_gi[(size_t)2*MTOT*N3];    // precomputed x@Wih^T
__device__ unsigned g_bar2[2];               // per-dir barrier counters

// ---------------- helpers ----------------
__device__ __forceinline__ void cp16(f16* dst, const f16* src) {
    unsigned d = (unsigned)__cvta_generic_to_shared(dst);
    asm volatile("cp.async.cg.shared.global [%0], [%1], 16;\n" :: "r"(d), "l"(src));
}
__device__ __forceinline__ uint32_t smaddr(const void* p) {
    return (uint32_t)__cvta_generic_to_shared(p);
}
__device__ __forceinline__ void ldsm_x4(uint32_t r[4], uint32_t a) {
    asm volatile("ldmatrix.sync.aligned.m8n8.x4.shared.b16 {%0,%1,%2,%3},[%4];"
                 : "=r"(r[0]), "=r"(r[1]), "=r"(r[2]), "=r"(r[3]) : "r"(a));
}
__device__ __forceinline__ void mma16816(float c[4], const uint32_t a[4],
                                         uint32_t b0, uint32_t b1) {
    asm volatile(
        "mma.sync.aligned.m16n8k16.row.col.f32.f16.f16.f32 "
        "{%0,%1,%2,%3},{%4,%5,%6,%7},{%8,%9},{%0,%1,%2,%3};"
        : "+f"(c[0]), "+f"(c[1]), "+f"(c[2]), "+f"(c[3])
        : "r"(a[0]), "r"(a[1]), "r"(a[2]), "r"(a[3]), "r"(b0), "r"(b1));
}
__device__ __forceinline__ float fsig(float x) {
    return __fdividef(1.f, 1.f + __expf(-x));
}
__device__ __forceinline__ float ftanh(float x) {
    return 1.f - __fdividef(2.f, __expf(2.f * x) + 1.f);
}

#define CP_COMMIT() asm volatile("cp.async.commit_group;")

// ---------------- prep kernels ----------------
__global__ void pack_x_kernel(const float* __restrict__ x) {
    int i = blockIdx.x * 256 + threadIdx.x;
    g_x[i] = __float2half_rn(x[i]);
}

__global__ void pack_w_kernel(const float* __restrict__ Wih_f, const float* __restrict__ Whh_f,
                              const float* __restrict__ Wih_b, const float* __restrict__ Whh_b) {
    int idx = blockIdx.x * 256 + threadIdx.x;
    int k   = idx % KDIM;
    int n   = (idx / KDIM) % N3;
    int dir = idx / (KDIM * N3);
    int j = n / 3, g = n % 3;
    int srow = g * HDIM + j;
    const float* Wih = dir ? Wih_b : Wih_f;
    const float* Whh = dir ? Whh_b : Whh_f;
    float v = (k < IDIM) ? Wih[srow * IDIM + k] : Whh[srow * HDIM + (k - IDIM)];
    g_W[idx] = __float2half_rn(v);
}

__global__ void pack_bias_kernel(const float* __restrict__ bih_f, const float* __restrict__ bhh_f,
                                 const float* __restrict__ bih_b, const float* __restrict__ bhh_b) {
    int i = blockIdx.x * 256 + threadIdx.x;   // 0..2047
    int dir = i >> 10, j = i & 1023;
    const float* bih = dir ? bih_b : bih_f;
    const float* bhh = dir ? bhh_b : bhh_f;
    g_bias[dir][0][j] = bih[j] + bhh[j];
    g_bias[dir][1][j] = bih[HDIM + j] + bhh[HDIM + j];
    g_bias[dir][2][j] = bih[2 * HDIM + j];
    g_bias[dir][3][j] = bhh[2 * HDIM + j];
}

__global__ void init_h_kernel() {
    int i = blockIdx.x * 256 + threadIdx.x;   // 2*2*B*H
    g_hf[i] = __float2half_rn(0.f);
    if (i < 2) g_bar2[i] = 0u;
}

// ---------------- warp compute: 16 rows x (NT*8) cols over 32 k ----------------
template<int NT, int AST>
__device__ __forceinline__ void compute_tile(f16* pA, f16* pB, int mwarp, int ngrp,
                                             int lane, float acc[NT][4]) {
    const uint32_t aoff = smaddr(pA + (mwarp * 16 + (lane & 15)) * AST + (lane >> 4) * 8);
    const uint32_t boff = smaddr(pB + (ngrp * (NT * 8) + (lane & 7)) * AST + (lane >> 3) * 8);
    uint32_t a0[4], a1[4];
    ldsm_x4(a0, aoff);
    ldsm_x4(a1, aoff + 16 * 2);
#pragma unroll
    for (int nt = 0; nt < NT; ++nt) {
        uint32_t b4[4];
        ldsm_x4(b4, boff + nt * 8 * AST * 2);
        mma16816(acc[nt], a0, b4[0], b4[1]);
        mma16816(acc[nt], a1, b4[2], b4[3]);
    }
}

// ---------------- pre-GEMM: gi = x @ Wih^T (unchanged from R8/R9) ----------------
// grid: (NBLK_G=32, MTOT/128=512, 2), block 512 (16 warps: 8 M x 2 N)
__global__ void __launch_bounds__(512) gi_gemm() {
    extern __shared__ char smraw[];
    f16* sm = (f16*)smraw;

    const int nblk = blockIdx.x, mblk = blockIdx.y, dir = blockIdx.z;
    const int t = threadIdx.x, warp = t >> 5, lane = t & 31;
    const int mwarp = warp & 7, ngrp = warp >> 3;
    const int grp = lane >> 2, tq = lane & 3;

    auto stage = [&](int s) { return sm + s * STAGE_G; };

    auto copy_tile = [&](int kt, int buf) {
        f16* st = stage(buf);
        const int k0 = kt * KT;
        {
            int row = t >> 2;
            int kq  = (t & 3) * 8;
            size_t off = ((size_t)mblk * 128 + row) * IDIM + k0 + kq;
            cp16(st + row * ASTR + kq, g_x + off);
        }
        if (t < 4 * TN_G) {
            int nloc = t >> 2;
            int kq   = (t & 3) * 8;
            size_t off = ((size_t)(dir * N3 + nblk * TN_G + nloc)) * KDIM + k0 + kq;
            cp16(st + 128 * ASTR + nloc * ASTR + kq, g_W + off);
        }
    };

    float acc[6][4];
#pragma unroll
    for (int i = 0; i < 6; i++)
#pragma unroll
        for (int q = 0; q < 4; q++) acc[i][q] = 0.f;

    copy_tile(0, 0); CP_COMMIT();
    copy_tile(1, 1); CP_COMMIT();

    const int NKT = IDIM / KT;   // 32
#pragma unroll 1
    for (int kt = 0; kt < NKT; ++kt) {
        if (kt < NKT - 1) asm volatile("cp.async.wait_group 1;");
        else              asm volatile("cp.async.wait_group 0;");
        __syncthreads();
        if (kt + 2 < NKT) { copy_tile(kt + 2, (kt + 2) % NSTG); CP_COMMIT(); }
        compute_tile<6, ASTR>(stage(kt % NSTG), stage(kt % NSTG) + 128 * ASTR,
                              mwarp, ngrp, lane, acc);
    }

    const int m = mblk * 128 + mwarp * 16 + grp;
    const int colbase = nblk * TN_G + ngrp * 48 + tq * 2;
    float* d0 = g_gi + ((size_t)dir * MTOT + m) * N3;
    float* d1 = d0 + (size_t)8 * N3;
#pragma unroll
    for (int nt = 0; nt < 6; ++nt) {
        int col = colbase + nt * 8;
        d0[col]     = acc[nt][0];
        d0[col + 1] = acc[nt][1];
        d1[col]     = acc[nt][2];
        d1[col + 1] = acc[nt][3];
    }
}

// ---------------- persistent recurrent kernel ----------------
// grid: (NBLK_S=64, 2) = 128 CTAs, block 512. Whh resident in smem; per-dir barrier.
__global__ void __launch_bounds__(512) gru_persist(float* __restrict__ out) {
    extern __shared__ char smraw[];
    f16* sm  = (f16*)smraw;
    f16* wsm = sm + W_OFF;

    const int nblk = blockIdx.x, dir = blockIdx.y;
    const int t = threadIdx.x, warp = t >> 5, lane = t & 31;
    const int mwarp = warp & 7, ngrp = warp >> 3;
    const int grp = lane >> 2, tq = lane & 3;

    // ---- preload Whh tile: 16 chunks x 48 rows x 64 k (ASTRP-padded) ----
    for (int i = t; i < NKTP * TN_S * 8; i += 512) {
        int kt   = i / (TN_S * 8);
        int r    = i % (TN_S * 8);
        int nloc = r >> 3, kq = (r & 7) * 8;
        size_t off = ((size_t)(dir * N3 + nblk * TN_S + nloc)) * KDIM + IDIM + kt * KTP + kq;
        cp16(wsm + kt * W_CH + nloc * ASTRP + kq, g_W + off);
    }
    CP_COMMIT();
    asm volatile("cp.async.wait_group 0;");
    __syncthreads();

    // ---- per-thread persistent state: 4 (b, jj) pairs ----
    float hreg[4];
    float bs0[4], bs1[4], bs2[4], bs3[4];
    int   b_arr[4], jj_arr[4];
#pragma unroll
    for (int q = 0; q < 4; q++) {
        int p = t * 4 + q;
        int b = p >> 4, jj = p & 15;
        int j = nblk * 16 + jj;
        b_arr[q] = b; jj_arr[q] = jj;
        hreg[q] = 0.f;
        bs0[q] = g_bias[dir][0][j];
        bs1[q] = g_bias[dir][1][j];
        bs2[q] = g_bias[dir][2][j];
        bs3[q] = g_bias[dir][3][j];
    }

#pragma unroll 1
    for (int step = 0; step < S_LEN; ++step) {
        const int rpar = step & 1, wpar = rpar ^ 1;
        const int s_x  = dir ? (S_LEN - 1 - step) : step;

        // ---- prefetch gi for this step into registers (hidden behind mainloop) ----
        const float* gib = g_gi + ((size_t)dir * MTOT + (size_t)s_x * BATCH) * N3 + nblk * TN_S;
        float gi0[4], gi1[4], gi2[4];
#pragma unroll
        for (int q = 0; q < 4; q++) {
            const float* gp = gib + (size_t)b_arr[q] * N3 + jj_arr[q] * 3;
            gi0[q] = __ldg(gp);
            gi1[q] = __ldg(gp + 1);
            gi2[q] = __ldg(gp + 2);
        }

        auto copyA = [&](int kt, int buf) {
            f16* st = sm + buf * APLANE;
#pragma unroll
            for (int i = 0; i < 2; i++) {
                int idx = t + i * 512;
                int row = idx >> 3, kq = (idx & 7) * 8;
                int off = ((rpar * 2 + dir) * BATCH + row) * HDIM + kt * KTP + kq;
                cp16(st + row * ASTRP + kq, g_hf + off);
            }
        };

        float acc[3][4];
#pragma unroll
        for (int i = 0; i < 3; i++)
#pragma unroll
            for (int q = 0; q < 4; q++) acc[i][q] = 0.f;

        copyA(0, 0); CP_COMMIT();
        copyA(1, 1); CP_COMMIT();

#pragma unroll 1
        for (int kt = 0; kt < NKTP; ++kt) {
            if (kt < NKTP - 1) asm volatile("cp.async.wait_group 1;");
            else               asm volatile("cp.async.wait_group 0;");
            __syncthreads();
            if (kt + 2 < NKTP) { copyA(kt + 2, (kt + 2) % NSTG); CP_COMMIT(); }
            f16* pA = sm + (kt % NSTG) * APLANE;
            f16* pW = wsm + kt * W_CH;
            compute_tile<3, ASTRP>(pA, pW, mwarp, ngrp, lane, acc);
            compute_tile<3, ASTRP>(pA + 32, pW + 32, mwarp, ngrp, lane, acc);
        }

        // ---- epilogue: accumulators -> smem (overlays A stages), gates ----
        __syncthreads();
        float* sC = (float*)smraw;   // [128][49] = 25088 B < 3*APLANE*2
        {
            const int row  = mwarp * 16 + grp;
            const int colb = ngrp * 24 + tq * 2;
#pragma unroll
            for (int nt = 0; nt < 3; ++nt) {
                int col = colb + nt * 8;
                sC[row * 49 + col]           = acc[nt][0];
                sC[row * 49 + col + 1]       = acc[nt][1];
                sC[(row + 8) * 49 + col]     = acc[nt][2];
                sC[(row + 8) * 49 + col + 1] = acc[nt][3];
            }
        }
        __syncthreads();

#pragma unroll
        for (int q = 0; q < 4; q++) {
            int b = b_arr[q], jj = jj_arr[q];
            int j = nblk * 16 + jj;
            int c = jj * 3;
            float gr  = sC[b * 49 + c]     + gi0[q] + bs0[q];
            float gz  = sC[b * 49 + c + 1] + gi1[q] + bs1[q];
            float gnh = sC[b * 49 + c + 2] + bs3[q];
            float gni = gi2[q] + bs2[q];
            float r = fsig(gr);
            float z = fsig(gz);
            float n = ftanh(gni + r * gnh);
            float hnew = (1.f - z) * n + z * hreg[q];
            hreg[q] = hnew;
            g_hf[((wpar * 2 + dir) * BATCH + b) * HDIM + j] = __float2half_rn(hnew);
            out[((size_t)step * BATCH + b) * (2 * HDIM) + dir * HDIM + j] = hnew;
        }

        // ---- per-direction grid barrier (64 CTAs) ----
        if (step < S_LEN - 1) {
            __syncthreads();
            if (t == 0) {
                __threadfence();
                atomicAdd(&g_bar2[dir], 1u);
                unsigned target = (unsigned)NBLK_S * (unsigned)(step + 1);
                while (*(volatile unsigned*)&g_bar2[dir] < target) __nanosleep(32);
                __threadfence();
            }
            __syncthreads();
        }
    }
}

// ---------------- launch ----------------
extern "C" void kernel_launch(void* const* d_in, const int* in_sizes, int n_in,
                              void* d_out, int out_size) {
    const float* x     = (const float*)d_in[0];
    const float* Wih_f = (const float*)d_in[1];
    const float* Whh_f = (const float*)d_in[2];
    const float* bih_f = (const float*)d_in[3];
    const float* bhh_f = (const float*)d_in[4];
    const float* Wih_b = (const float*)d_in[5];
    const float* Whh_b = (const float*)d_in[6];
    const float* bih_b = (const float*)d_in[7];
    const float* bhh_b = (const float*)d_in[8];
    float* out = (float*)d_out;

    cudaFuncSetAttribute(gi_gemm,     cudaFuncAttributeMaxDynamicSharedMemorySize, SMEM_G);
    cudaFuncSetAttribute(gru_persist, cudaFuncAttributeMaxDynamicSharedMemorySize, SMEM_P);

    pack_x_kernel<<<(int)((size_t)MTOT * IDIM / 256), 256>>>(x);
    pack_w_kernel<<<2 * N3 * KDIM / 256, 256>>>(Wih_f, Whh_f, Wih_b, Whh_b);
    pack_bias_kernel<<<8, 256>>>(bih_f, bhh_f, bih_b, bhh_b);
    init_h_kernel<<<2 * 2 * BATCH * HDIM / 256, 256>>>();

    gi_gemm<<<dim3(NBLK_G, MTOT / 128, 2), 512, SMEM_G>>>();

    gru_persist<<<dim3(NBLK_S, 2), 512, SMEM_P>>>(out);
}

// round 11
// speedup vs baseline: 4.4244x; 1.1808x over previous
#include <cuda_runtime.h>
#include <cuda_fp16.h>
#include <stdint.h>

typedef __half f16;

#define S_LEN 512
#define BATCH 128
#define IDIM  1024
#define HDIM  1024
#define KDIM  2048       // packed weights: k<1024 -> Wih, k>=1024 -> Whh
#define N3    3072       // 3 gates * H, interleaved col = 3*j + gate
#define MTOT  (S_LEN*BATCH)

#define TN_S  48               // step N tile (2 ngrp x 24)
#define TN_G  96               // gi N tile   (2 ngrp x 48)
#define NBLK_S (N3/TN_S)       // 64
#define NBLK_G (N3/TN_G)       // 32

// ---- gi GEMM layout (KT=32/ASTR=40) ----
#define KT    32
#define ASTR  40
#define NSTG  3
#define STAGE_G ((128 + TN_G)*ASTR)        // 8960 f16
#define SMEM_G  (NSTG*STAGE_G*2)           // 53760 B

// ---- persistent kernel layout (KT=64 / ASTR=72, pair-private A) ----
#define KTP    64
#define ASTRP  72
#define NKTP   (HDIM/KTP)                  // 16
#define APAIR  (16*ASTRP)                  // 1152 f16 per pair stage
#define APBLK  (NSTG*APAIR)                // 3456 f16 per pair
#define W_OFF  (8*APBLK)                   // 27648 f16
#define W_CH   (TN_S*ASTRP)                // 3456 f16 per k-chunk
#define SMEM_P ((W_OFF + NKTP*W_CH)*2)     // 165888 B

// ---------------- device scratch ----------------
__device__ f16   g_x[(size_t)MTOT*IDIM];
__device__ f16   g_W[(size_t)2*N3*KDIM];     // [dir][n][k] fp16
__device__ float g_bias[2][4][HDIM];         // br, bz, b_in, b_hn
__device__ f16   g_hf[2*2*BATCH*HDIM];       // [parity][dir][b][j]
__device__ float g_gi[(size_t)2*MTOT*N3];    // precomputed x@Wih^T
__device__ unsigned g_bar2[2];               // per-dir barrier counters

// ---------------- helpers ----------------
__device__ __forceinline__ void cp16(f16* dst, const f16* src) {
    unsigned d = (unsigned)__cvta_generic_to_shared(dst);
    asm volatile("cp.async.cg.shared.global [%0], [%1], 16;\n" :: "r"(d), "l"(src));
}
__device__ __forceinline__ uint32_t smaddr(const void* p) {
    return (uint32_t)__cvta_generic_to_shared(p);
}
__device__ __forceinline__ void ldsm_x4(uint32_t r[4], uint32_t a) {
    asm volatile("ldmatrix.sync.aligned.m8n8.x4.shared.b16 {%0,%1,%2,%3},[%4];"
                 : "=r"(r[0]), "=r"(r[1]), "=r"(r[2]), "=r"(r[3]) : "r"(a));
}
__device__ __forceinline__ void mma16816(float c[4], const uint32_t a[4],
                                         uint32_t b0, uint32_t b1) {
    asm volatile(
        "mma.sync.aligned.m16n8k16.row.col.f32.f16.f16.f32 "
        "{%0,%1,%2,%3},{%4,%5,%6,%7},{%8,%9},{%0,%1,%2,%3};"
        : "+f"(c[0]), "+f"(c[1]), "+f"(c[2]), "+f"(c[3])
        : "r"(a[0]), "r"(a[1]), "r"(a[2]), "r"(a[3]), "r"(b0), "r"(b1));
}
__device__ __forceinline__ float fsig(float x) {
    return __fdividef(1.f, 1.f + __expf(-x));
}
__device__ __forceinline__ float ftanh(float x) {
    return 1.f - __fdividef(2.f, __expf(2.f * x) + 1.f);
}
__device__ __forceinline__ void bar_pair(int id) {
    asm volatile("bar.sync %0, 64;" :: "r"(id) : "memory");
}

#define CP_COMMIT() asm volatile("cp.async.commit_group;")

// ---------------- prep kernels ----------------
__global__ void pack_x_kernel(const float* __restrict__ x) {
    int i = blockIdx.x * 256 + threadIdx.x;
    g_x[i] = __float2half_rn(x[i]);
}

__global__ void pack_w_kernel(const float* __restrict__ Wih_f, const float* __restrict__ Whh_f,
                              const float* __restrict__ Wih_b, const float* __restrict__ Whh_b) {
    int idx = blockIdx.x * 256 + threadIdx.x;
    int k   = idx % KDIM;
    int n   = (idx / KDIM) % N3;
    int dir = idx / (KDIM * N3);
    int j = n / 3, g = n % 3;
    int srow = g * HDIM + j;
    const float* Wih = dir ? Wih_b : Wih_f;
    const float* Whh = dir ? Whh_b : Whh_f;
    float v = (k < IDIM) ? Wih[srow * IDIM + k] : Whh[srow * HDIM + (k - IDIM)];
    g_W[idx] = __float2half_rn(v);
}

__global__ void pack_bias_kernel(const float* __restrict__ bih_f, const float* __restrict__ bhh_f,
                                 const float* __restrict__ bih_b, const float* __restrict__ bhh_b) {
    int i = blockIdx.x * 256 + threadIdx.x;   // 0..2047
    int dir = i >> 10, j = i & 1023;
    const float* bih = dir ? bih_b : bih_f;
    const float* bhh = dir ? bhh_b : bhh_f;
    g_bias[dir][0][j] = bih[j] + bhh[j];
    g_bias[dir][1][j] = bih[HDIM + j] + bhh[HDIM + j];
    g_bias[dir][2][j] = bih[2 * HDIM + j];
    g_bias[dir][3][j] = bhh[2 * HDIM + j];
}

__global__ void init_h_kernel() {
    int i = blockIdx.x * 256 + threadIdx.x;   // 2*2*B*H
    g_hf[i] = __float2half_rn(0.f);
    if (i < 2) g_bar2[i] = 0u;
}

// ---------------- warp compute over 32 k (generic, used by gi_gemm) ----------------
template<int NT, int AST>
__device__ __forceinline__ void compute_tile(f16* pA, f16* pB, int mwarp, int ngrp,
                                             int lane, float acc[NT][4]) {
    const uint32_t aoff = smaddr(pA + (mwarp * 16 + (lane & 15)) * AST + (lane >> 4) * 8);
    const uint32_t boff = smaddr(pB + (ngrp * (NT * 8) + (lane & 7)) * AST + (lane >> 3) * 8);
    uint32_t a0[4], a1[4];
    ldsm_x4(a0, aoff);
    ldsm_x4(a1, aoff + 16 * 2);
#pragma unroll
    for (int nt = 0; nt < NT; ++nt) {
        uint32_t b4[4];
        ldsm_x4(b4, boff + nt * 8 * AST * 2);
        mma16816(acc[nt], a0, b4[0], b4[1]);
        mma16816(acc[nt], a1, b4[2], b4[3]);
    }
}

// pair-local variant: A buffer holds only this pair's 16 rows
template<int NT>
__device__ __forceinline__ void compute_pair(f16* pA, f16* pW, int ngrp,
                                             int lane, float acc[NT][4]) {
    const uint32_t aoff = smaddr(pA + (lane & 15) * ASTRP + (lane >> 4) * 8);
    const uint32_t boff = smaddr(pW + (ngrp * (NT * 8) + (lane & 7)) * ASTRP + (lane >> 3) * 8);
    uint32_t a0[4], a1[4];
    ldsm_x4(a0, aoff);
    ldsm_x4(a1, aoff + 16 * 2);
#pragma unroll
    for (int nt = 0; nt < NT; ++nt) {
        uint32_t b4[4];
        ldsm_x4(b4, boff + nt * 8 * ASTRP * 2);
        mma16816(acc[nt], a0, b4[0], b4[1]);
        mma16816(acc[nt], a1, b4[2], b4[3]);
    }
}

// ---------------- pre-GEMM: gi = x @ Wih^T (unchanged from R10) ----------------
// grid: (NBLK_G=32, MTOT/128=512, 2), block 512 (16 warps: 8 M x 2 N)
__global__ void __launch_bounds__(512) gi_gemm() {
    extern __shared__ char smraw[];
    f16* sm = (f16*)smraw;

    const int nblk = blockIdx.x, mblk = blockIdx.y, dir = blockIdx.z;
    const int t = threadIdx.x, warp = t >> 5, lane = t & 31;
    const int mwarp = warp & 7, ngrp = warp >> 3;
    const int grp = lane >> 2, tq = lane & 3;

    auto stage = [&](int s) { return sm + s * STAGE_G; };

    auto copy_tile = [&](int kt, int buf) {
        f16* st = stage(buf);
        const int k0 = kt * KT;
        {
            int row = t >> 2;
            int kq  = (t & 3) * 8;
            size_t off = ((size_t)mblk * 128 + row) * IDIM + k0 + kq;
            cp16(st + row * ASTR + kq, g_x + off);
        }
        if (t < 4 * TN_G) {
            int nloc = t >> 2;
            int kq   = (t & 3) * 8;
            size_t off = ((size_t)(dir * N3 + nblk * TN_G + nloc)) * KDIM + k0 + kq;
            cp16(st + 128 * ASTR + nloc * ASTR + kq, g_W + off);
        }
    };

    float acc[6][4];
#pragma unroll
    for (int i = 0; i < 6; i++)
#pragma unroll
        for (int q = 0; q < 4; q++) acc[i][q] = 0.f;

    copy_tile(0, 0); CP_COMMIT();
    copy_tile(1, 1); CP_COMMIT();

    const int NKT = IDIM / KT;   // 32
#pragma unroll 1
    for (int kt = 0; kt < NKT; ++kt) {
        if (kt < NKT - 1) asm volatile("cp.async.wait_group 1;");
        else              asm volatile("cp.async.wait_group 0;");
        __syncthreads();
        if (kt + 2 < NKT) { copy_tile(kt + 2, (kt + 2) % NSTG); CP_COMMIT(); }
        compute_tile<6, ASTR>(stage(kt % NSTG), stage(kt % NSTG) + 128 * ASTR,
                              mwarp, ngrp, lane, acc);
    }

    const int m = mblk * 128 + mwarp * 16 + grp;
    const int colbase = nblk * TN_G + ngrp * 48 + tq * 2;
    float* d0 = g_gi + ((size_t)dir * MTOT + m) * N3;
    float* d1 = d0 + (size_t)8 * N3;
#pragma unroll
    for (int nt = 0; nt < 6; ++nt) {
        int col = colbase + nt * 8;
        d0[col]     = acc[nt][0];
        d0[col + 1] = acc[nt][1];
        d1[col]     = acc[nt][2];
        d1[col + 1] = acc[nt][3];
    }
}

// ---------------- persistent recurrent kernel ----------------
// grid: (NBLK_S=64, 2) = 128 CTAs, block 512 (8 warp-pairs).
// Pair-private A staging + named pair barriers; ONE __syncthreads per step.
__global__ void __launch_bounds__(512) gru_persist(float* __restrict__ out) {
    extern __shared__ char smraw[];
    f16* sm  = (f16*)smraw;
    f16* wsm = sm + W_OFF;

    const int nblk = blockIdx.x, dir = blockIdx.y;
    const int t = threadIdx.x, warp = t >> 5, lane = t & 31;
    const int mwarp = warp & 7, ngrp = warp >> 3;
    const int grp = lane >> 2, tq = lane & 3;
    const int u = lane + (ngrp << 5);            // pair-local thread id 0..63
    const int barid = mwarp + 1;                 // named barrier per pair
    f16* apair = sm + mwarp * APBLK;

    // ---- preload Whh tile: 16 chunks x 48 rows x 64 k ----
    for (int i = t; i < NKTP * TN_S * 8; i += 512) {
        int kt   = i / (TN_S * 8);
        int r    = i % (TN_S * 8);
        int nloc = r >> 3, kq = (r & 7) * 8;
        size_t off = ((size_t)(dir * N3 + nblk * TN_S + nloc)) * KDIM + IDIM + kt * KTP + kq;
        cp16(wsm + kt * W_CH + nloc * ASTRP + kq, g_W + off);
    }
    CP_COMMIT();
    asm volatile("cp.async.wait_group 0;");
    __syncthreads();

    // ---- per-thread persistent state: one b, 4 consecutive j ----
    const int brow = mwarp * 16 + (u >> 2);          // batch row
    const int jb   = nblk * 16 + (u & 3) * 4;        // first j of 4
    const int c0   = (u & 3) * 12;                   // first col in pair's 48-col tile
    float hreg[4];
    float bs0[4], bs1[4], bs2[4], bs3[4];
#pragma unroll
    for (int q = 0; q < 4; q++) {
        hreg[q] = 0.f;
        bs0[q] = g_bias[dir][0][jb + q];
        bs1[q] = g_bias[dir][1][jb + q];
        bs2[q] = g_bias[dir][2][jb + q];
        bs3[q] = g_bias[dir][3][jb + q];
    }

#pragma unroll 1
    for (int step = 0; step < S_LEN; ++step) {
        const int rpar = step & 1, wpar = rpar ^ 1;
        const int s_x  = dir ? (S_LEN - 1 - step) : step;
        const int hbase = (rpar * 2 + dir) * BATCH * HDIM;

        auto copyA = [&](int kt, int buf) {
            f16* st = apair + buf * APAIR;
#pragma unroll
            for (int i = 0; i < 2; i++) {
                int slot = u + 64 * i;               // 128 slots: 16 rows x 8 kq
                int rl = slot >> 3, kq = (slot & 7) * 8;
                int off = hbase + (mwarp * 16 + rl) * HDIM + kt * KTP + kq;
                cp16(st + rl * ASTRP + kq, g_hf + off);
            }
        };

        float acc[3][4];
#pragma unroll
        for (int i = 0; i < 3; i++)
#pragma unroll
            for (int q = 0; q < 4; q++) acc[i][q] = 0.f;

        copyA(0, 0); CP_COMMIT();
        copyA(1, 1); CP_COMMIT();

        // ---- prefetch gi (12 consecutive floats) — hidden behind mainloop ----
        const float* gp = g_gi + ((size_t)dir * MTOT + (size_t)s_x * BATCH + brow) * N3
                          + nblk * TN_S + c0;
        float4 giA = __ldg((const float4*)gp);
        float4 giB = __ldg((const float4*)(gp + 4));
        float4 giC = __ldg((const float4*)(gp + 8));
        float giv[12] = {giA.x, giA.y, giA.z, giA.w, giB.x, giB.y, giB.z, giB.w,
                         giC.x, giC.y, giC.z, giC.w};

#pragma unroll 1
        for (int kt = 0; kt < NKTP; ++kt) {
            if (kt < NKTP - 1) asm volatile("cp.async.wait_group 1;");
            else               asm volatile("cp.async.wait_group 0;");
            bar_pair(barid);
            if (kt + 2 < NKTP) { copyA(kt + 2, (kt + 2) % NSTG); CP_COMMIT(); }
            f16* pA = apair + (kt % NSTG) * APAIR;
            f16* pW = wsm + kt * W_CH;
            compute_pair<3>(pA, pW, ngrp, lane, acc);
            compute_pair<3>(pA + 32, pW + 32, ngrp, lane, acc);
        }

        // ---- pair-local epilogue: frags -> pair smem -> gates ----
        bar_pair(barid);                              // A region reads done
        float* sCp = (float*)apair;                   // 16 x 49 floats (3136 B)
        {
            const int colb = ngrp * 24 + tq * 2;
#pragma unroll
            for (int nt = 0; nt < 3; ++nt) {
                int col = colb + nt * 8;
                sCp[grp * 49 + col]           = acc[nt][0];
                sCp[grp * 49 + col + 1]       = acc[nt][1];
                sCp[(grp + 8) * 49 + col]     = acc[nt][2];
                sCp[(grp + 8) * 49 + col + 1] = acc[nt][3];
            }
        }
        bar_pair(barid);

        const float* sRow = sCp + (u >> 2) * 49 + c0;
#pragma unroll
        for (int q = 0; q < 4; q++) {
            float gr  = sRow[q * 3]     + giv[q * 3]     + bs0[q];
            float gz  = sRow[q * 3 + 1] + giv[q * 3 + 1] + bs1[q];
            float gnh = sRow[q * 3 + 2] + bs3[q];
            float gni = giv[q * 3 + 2] + bs2[q];
            float r = fsig(gr);
            float z = fsig(gz);
            float n = ftanh(gni + r * gnh);
            hreg[q] = (1.f - z) * n + z * hreg[q];
        }
        // packed h store (4 consecutive f16 = 8 B)
        {
            __half2 lo2 = __halves2half2(__float2half_rn(hreg[0]), __float2half_rn(hreg[1]));
            __half2 hi2 = __halves2half2(__float2half_rn(hreg[2]), __float2half_rn(hreg[3]));
            uint2 v;
            v.x = *(const unsigned*)&lo2;
            v.y = *(const unsigned*)&hi2;
            *(uint2*)(g_hf + ((wpar * 2 + dir) * BATCH + brow) * HDIM + jb) = v;
        }

        __syncthreads();
        if (step < S_LEN - 1 && t == 0) {
            __threadfence();
            atomicAdd(&g_bar2[dir], 1u);
        }

        // out store (float4) overlaps barrier wait
        {
            float4 o = make_float4(hreg[0], hreg[1], hreg[2], hreg[3]);
            *(float4*)(out + ((size_t)step * BATCH + brow) * (2 * HDIM) + dir * HDIM + jb) = o;
        }

        if (step < S_LEN - 1) {
            if (t == 0) {
                unsigned target = (unsigned)NBLK_S * (unsigned)(step + 1);
                while (*(volatile unsigned*)&g_bar2[dir] < target) __nanosleep(32);
                __threadfence();
            }
            __syncthreads();
        }
    }
}

// ---------------- launch ----------------
extern "C" void kernel_launch(void* const* d_in, const int* in_sizes, int n_in,
                              void* d_out, int out_size) {
    const float* x     = (const float*)d_in[0];
    const float* Wih_f = (const float*)d_in[1];
    const float* Whh_f = (const float*)d_in[2];
    const float* bih_f = (const float*)d_in[3];
    const float* bhh_f = (const float*)d_in[4];
    const float* Wih_b = (const float*)d_in[5];
    const float* Whh_b = (const float*)d_in[6];
    const float* bih_b = (const float*)d_in[7];
    const float* bhh_b = (const float*)d_in[8];
    float* out = (float*)d_out;

    cudaFuncSetAttribute(gi_gemm,     cudaFuncAttributeMaxDynamicSharedMemorySize, SMEM_G);
    cudaFuncSetAttribute(gru_persist, cudaFuncAttributeMaxDynamicSharedMemorySize, SMEM_P);

    pack_x_kernel<<<(int)((size_t)MTOT * IDIM / 256), 256>>>(x);
    pack_w_kernel<<<2 * N3 * KDIM / 256, 256>>>(Wih_f, Whh_f, Wih_b, Whh_b);
    pack_bias_kernel<<<8, 256>>>(bih_f, bhh_f, bih_b, bhh_b);
    init_h_kernel<<<2 * 2 * BATCH * HDIM / 256, 256>>>();

    gi_gemm<<<dim3(NBLK_G, MTOT / 128, 2), 512, SMEM_G>>>();

    gru_persist<<<dim3(NBLK_S, 2), 512, SMEM_P>>>(out);
}